// round 10
// baseline (speedup 1.0000x reference)
#include <cuda_runtime.h>
#include <cuda.h>
#include <stdint.h>

// Problem constants
#define Bn 8
#define Sn 1024
#define En 768
#define Hn 12
#define F3 2304          // 3*E
#define NQKV 27648       // H*3E
#define HE 9216          // H*E

// Scratch (allocation-free: __device__ globals)
__device__ float g_qkv[(size_t)Bn * Hn * Sn * F3];     // [B,H,S,3E] (tf32-rounded)
__device__ float g_scores[(size_t)Bn * Hn * Sn * Sn];  // [B*H,S,S]
__device__ float g_vT[(size_t)Bn * Hn * En * Sn];      // [B*H,E,S]  (tf32-rounded)
__device__ float g_concat[(size_t)Bn * Sn * Hn * En];  // [B,S,H,E]  (tf32-rounded)
__device__ float g_xr[(size_t)Bn * Sn * En];           // rounded x
__device__ float g_wqkvr[(size_t)NQKV * En];           // rounded qkv_w
__device__ float g_owr[(size_t)En * HE];               // rounded out_w

struct GemmParams {
    const float* A;   // [M,K] K-major (fallback only)
    const float* B;   // [N,K] K-major (fallback only)
    float* C;
    int K;
    int lda, ldb, ldc;
    long long strideAz, strideBz;
    long long strideCb, strideCh;
    int divH;
    const float* bias;
    float alpha;
};

__device__ __forceinline__ uint32_t f2tf32(float x) {
    uint32_t r;
    asm("cvt.rna.tf32.f32 %0, %1;" : "=r"(r) : "f"(x));
    return r;
}

__device__ __forceinline__ uint32_t smem_u32_g(const void* p) {
    uint32_t a;
    asm("{ .reg .u64 t; cvta.to.shared.u64 t, %1; cvt.u32.u64 %0, t; }"
        : "=r"(a) : "l"(p));
    return a;
}

#if defined(__CUDA_ARCH_FEAT_SM103_ALL)
// ---------- sm_103a-only helpers ----------
__device__ __forceinline__ uint32_t elect_one() {
    uint32_t p;
    asm volatile(
        "{\n\t.reg .pred p;\n\telect.sync _|p, 0xFFFFFFFF;\n\t"
        "selp.b32 %0, 1, 0, p;\n\t}" : "=r"(p));
    return p;
}

#define TCGEN05_ALLOC(a, n) \
    asm volatile("tcgen05.alloc.cta_group::1.sync.aligned.shared::cta.b32 [%0], %1;" \
                 :: "r"(a), "r"(n) : "memory")
#define TCGEN05_DEALLOC(t, n) \
    asm volatile("tcgen05.dealloc.cta_group::1.sync.aligned.b32 %0, %1;" :: "r"(t), "r"(n))
#define TCGEN05_RELINQ() \
    asm volatile("tcgen05.relinquish_alloc_permit.cta_group::1.sync.aligned;")
#define TCGEN05_COMMIT(m) \
    asm volatile("tcgen05.commit.cta_group::1.mbarrier::arrive::one.shared::cluster.b64 [%0];" \
                 :: "r"(m) : "memory")
#define MBARRIER_INIT(m, c) \
    asm volatile("mbarrier.init.shared.b64 [%0], %1;" :: "r"(m), "r"(c) : "memory")
#define MBARRIER_INVAL(m) \
    asm volatile("mbarrier.inval.shared.b64 [%0];" :: "r"(m) : "memory")
#define MBARRIER_EXPECT_TX(m, b) \
    asm volatile("mbarrier.arrive.expect_tx.shared.b64 _, [%0], %1;" \
                 :: "r"(m), "r"(b) : "memory")
#define TCGEN05_FENCE_AFTER()  asm volatile("tcgen05.fence::after_thread_sync;" ::: "memory")
#define TCGEN05_FENCE_BEFORE() asm volatile("tcgen05.fence::before_thread_sync;" ::: "memory")
#define TCGEN05_WAIT_LD()      asm volatile("tcgen05.wait::ld.sync.aligned;" ::: "memory")
#define FENCE_ASYNC()          asm volatile("fence.proxy.async.shared::cta;" ::: "memory")

#define TMA3D(sm, mapp, cx, cy, cz, mb) \
    asm volatile( \
        "cp.async.bulk.tensor.3d.shared::cta.global.tile.mbarrier::complete_tx::bytes " \
        "[%0], [%1, {%2, %3, %4}], [%5];" \
        :: "r"(sm), "l"(mapp), "r"(cx), "r"(cy), "r"(cz), "r"(mb) : "memory")

#define MBARRIER_WAIT_PARITY(mbar_smem_addr, phase_parity) do { \
    uint32_t _mbar = (uint32_t)(mbar_smem_addr); \
    uint32_t _parity = (uint32_t)(phase_parity); \
    uint32_t _done; \
    asm volatile( \
        "{\n\t.reg .pred p;\n\t" \
        "mbarrier.try_wait.parity.acquire.cta.shared::cta.b64 p, [%1], %2;\n\t" \
        "selp.b32 %0, 1, 0, p;\n\t}" \
        : "=r"(_done) : "r"(_mbar), "r"(_parity) : "memory"); \
    if (!_done) { \
        asm volatile( \
            "{\n\t.reg .pred P1;\n\t" \
            "WAIT_LOOP_%=:\n\t" \
            "mbarrier.try_wait.parity.acquire.cta.shared::cta.b64 P1, [%0], %1, 0x989680;\n\t" \
            "@P1 bra.uni WAIT_DONE_%=;\n\t" \
            "bra.uni WAIT_LOOP_%=;\n\t" \
            "WAIT_DONE_%=:\n\t}" \
            :: "r"(_mbar), "r"(_parity) : "memory"); \
    } \
} while (0)

#define TCGEN05_LD_32X32B_X32(r, tmem_addr) \
    asm volatile( \
        "tcgen05.ld.sync.aligned.32x32b.x32.b32 " \
        "{%0, %1, %2, %3, %4, %5, %6, %7, " \
        " %8, %9, %10, %11, %12, %13, %14, %15, " \
        " %16, %17, %18, %19, %20, %21, %22, %23, " \
        " %24, %25, %26, %27, %28, %29, %30, %31}, [%32];" \
        : "=r"((r)[0]),  "=r"((r)[1]),  "=r"((r)[2]),  "=r"((r)[3]), \
          "=r"((r)[4]),  "=r"((r)[5]),  "=r"((r)[6]),  "=r"((r)[7]), \
          "=r"((r)[8]),  "=r"((r)[9]),  "=r"((r)[10]), "=r"((r)[11]), \
          "=r"((r)[12]), "=r"((r)[13]), "=r"((r)[14]), "=r"((r)[15]), \
          "=r"((r)[16]), "=r"((r)[17]), "=r"((r)[18]), "=r"((r)[19]), \
          "=r"((r)[20]), "=r"((r)[21]), "=r"((r)[22]), "=r"((r)[23]), \
          "=r"((r)[24]), "=r"((r)[25]), "=r"((r)[26]), "=r"((r)[27]), \
          "=r"((r)[28]), "=r"((r)[29]), "=r"((r)[30]), "=r"((r)[31]) \
        : "r"(tmem_addr))

// SW128 K-major SMEM descriptor (128B rows): layout=SW128, version=1, SBO=64, LBO=1
static __device__ __forceinline__ uint64_t mk_desc(uint32_t addr) {
    const uint64_t base = (2ULL << 61) | (1ULL << 46) | (64ULL << 32) | (1ULL << 16);
    return base | ((uint64_t)(addr >> 4) & 0x3FFF);
}

// idesc kind::tf32: dtype F32=1 @bit4, atype=btype=TF32=2 @bits7/10,
// N/8 @bit17, M/16 @bit24   (M=128, N=256)
#define IDESC_TF32 ((1u << 4) | (2u << 7) | (2u << 10) | (32u << 17) | (8u << 24))

__device__ __forceinline__ void mma_tf32_ss(uint32_t d_tmem, uint64_t ad, uint64_t bd,
                                            uint32_t en) {
    asm volatile(
        "{\n\t.reg .pred pq;\n\tsetp.ne.u32 pq, %5, 0;\n\t"
        "tcgen05.mma.cta_group::1.kind::tf32 [%0], %1, %2, %3, {%4, %4, %4, %4}, pq;\n\t}"
        :: "r"(d_tmem), "l"(ad), "l"(bd), "r"(IDESC_TF32), "r"(0u), "r"(en)
        : "memory");
}
#endif  // __CUDA_ARCH_FEAT_SM103_ALL

// ---------- GEMM: A[M,K] x B[N,K]^T, tile (128*MH)x256, 256 threads ----------
// sm_103a: TMA-fed double-buffered tcgen05 SS pipeline. MH=2 -> 256-row tiles,
// two M=128 MMAs per chunk into TMEM cols [0,256) and [256,512).
// EPI: 0 = plain C write, 1 = QKV scatter. ROUND: round stored values to tf32.
template <int MH, int EPI, int ROUND>
__global__ void __launch_bounds__(256) gemm_tma(
    const __grid_constant__ CUtensorMap mA,
    const __grid_constant__ CUtensorMap mB,
    GemmParams p)
{
    extern __shared__ __align__(16) float smem_raw[];
    const int tid = threadIdx.x;
    const int lane = tid & 31;
    const int wid = tid >> 5;
    const int bn = blockIdx.x, bm = blockIdx.y, z = blockIdx.z;
    const size_t coff = (size_t)(z / p.divH) * p.strideCb +
                        (size_t)(z % p.divH) * p.strideCh;

#if defined(__CUDA_ARCH_FEAT_SM103_ALL)
    __shared__ uint32_t s_tmem;
    __shared__ __align__(8) unsigned long long s_mbar[4];  // full0 full1 done0 done1

    const uint32_t raw_u  = smem_u32_g(smem_raw);
    const uint32_t smem_u = (raw_u + 1023u) & ~1023u;   // SW128 atom alignment
    const uint32_t mbar   = smem_u32_g(s_mbar);

    constexpr uint32_t ASZ = MH * 16384u;       // A stage bytes
    constexpr uint32_t SZ  = ASZ + 32768u;      // stage bytes (A+B)
    constexpr uint32_t TCOLS = MH * 256u;

    if (wid == 0) { TCGEN05_ALLOC(smem_u32_g(&s_tmem), TCOLS); TCGEN05_RELINQ(); }
    if (tid == 0) {
        MBARRIER_INIT(mbar + 0, 1);  MBARRIER_INIT(mbar + 8, 1);
        MBARRIER_INIT(mbar + 16, 1); MBARRIER_INIT(mbar + 24, 1);
        FENCE_ASYNC();
    }
    __syncthreads();
    const uint32_t tmem = s_tmem;

    const int nIter = p.K >> 5;   // 24 / 32 / 288, always even >= 2

    if (wid == 0) {
        if (elect_one()) {
            const CUtensorMap* pA = &mA;
            const CUtensorMap* pB = &mB;
            const int m0 = bm * (128 * MH);
            const int n0 = bn * 256;
            int phf0 = 0, phf1 = 0, phd0 = 0, phd1 = 0;

            MBARRIER_EXPECT_TX(mbar + 0, SZ);
            TMA3D(smem_u, pA, 0, m0, z, mbar + 0);
            TMA3D(smem_u + ASZ, pB, 0, n0, z, mbar + 0);

            for (int kt = 0; kt < nIter; kt++) {
                const int buf = kt & 1;
                if (kt + 1 < nIter) {
                    const int nb = buf ^ 1;
                    if (kt >= 1) {   // prior MMA on nb must be done reading
                        if (nb == 0) { MBARRIER_WAIT_PARITY(mbar + 16, phd0); phd0 ^= 1; }
                        else         { MBARRIER_WAIT_PARITY(mbar + 24, phd1); phd1 ^= 1; }
                    }
                    const uint32_t oa = smem_u + nb * SZ;
                    MBARRIER_EXPECT_TX(mbar + nb * 8, SZ);
                    TMA3D(oa, pA, (kt + 1) * 32, m0, z, mbar + nb * 8);
                    TMA3D(oa + ASZ, pB, (kt + 1) * 32, n0, z, mbar + nb * 8);
                }
                if (buf == 0) { MBARRIER_WAIT_PARITY(mbar + 0, phf0); phf0 ^= 1; }
                else          { MBARRIER_WAIT_PARITY(mbar + 8, phf1); phf1 ^= 1; }
                const uint32_t oa = smem_u + buf * SZ;
                const uint64_t bd = mk_desc(oa + ASZ);
                #pragma unroll
                for (int ks = 0; ks < 4; ks++) {
                    #pragma unroll
                    for (int mh = 0; mh < MH; mh++) {
                        const uint64_t ad = mk_desc(oa + mh * 16384u);
                        mma_tf32_ss(tmem + mh * 256, ad + ks * 2, bd + ks * 2,
                                    (kt > 0 || ks > 0) ? 1u : 0u);
                    }
                }
                TCGEN05_COMMIT(mbar + 16 + buf * 8);
            }
            MBARRIER_WAIT_PARITY(mbar + 16, phd0);
            MBARRIER_WAIT_PARITY(mbar + 24, phd1);
        }
    }
    __syncthreads();
    TCGEN05_FENCE_AFTER();

    // Epilogue.
    // MH=2: warps 0-3 -> M-half 0 (TMEM cols 0-255), warps 4-7 -> M-half 1
    //       (cols 256-511). Each warp: 8 x 32-col slices covering n [0,256).
    // MH=1: warps 0-3 -> cols 0-127, warps 4-7 -> cols 128-255 (4 slices).
    const int nslice = (MH == 2) ? 8 : 4;
    const int m = bm * (128 * MH) +
                  ((MH == 2) ? (wid >> 2) * 128 : 0) + (wid & 3) * 32 + lane;
    const uint32_t tbase = tmem + ((MH == 2) ? (uint32_t)(wid >> 2) * 256u
                                             : (uint32_t)(wid >> 2) * 128u);
    const int nbase = bn * 256 + ((MH == 2) ? 0 : (wid >> 2) * 128);

    for (int i = 0; i < nslice; i++) {
        uint32_t r[32];
        TCGEN05_LD_32X32B_X32(r, tbase + i * 32);
        TCGEN05_WAIT_LD();
        const int n0 = nbase + i * 32;
        float* dst;
        if (EPI == 1) {
            const int b = m >> 10, s = m & 1023;
            const int h = n0 / F3, f = n0 - h * F3;
            dst = &g_qkv[(((size_t)(b * Hn + h)) * Sn + s) * F3 + f];
        } else {
            dst = &p.C[coff + (size_t)m * p.ldc + n0];
        }
        #pragma unroll
        for (int j = 0; j < 32; j += 4) {
            float4 v;
            v.x = __uint_as_float(r[j + 0]) * p.alpha;
            v.y = __uint_as_float(r[j + 1]) * p.alpha;
            v.z = __uint_as_float(r[j + 2]) * p.alpha;
            v.w = __uint_as_float(r[j + 3]) * p.alpha;
            if (p.bias) {
                float4 bb = *(const float4*)&p.bias[n0 + j];
                v.x += bb.x; v.y += bb.y; v.z += bb.z; v.w += bb.w;
            }
            if (ROUND) {
                v.x = __uint_as_float(f2tf32(v.x));
                v.y = __uint_as_float(f2tf32(v.y));
                v.z = __uint_as_float(f2tf32(v.z));
                v.w = __uint_as_float(f2tf32(v.w));
            }
            *(float4*)&dst[j] = v;
        }
    }
    TCGEN05_FENCE_BEFORE();

    __syncthreads();
    if (tid == 0) {
        MBARRIER_INVAL(mbar + 0);  MBARRIER_INVAL(mbar + 8);
        MBARRIER_INVAL(mbar + 16); MBARRIER_INVAL(mbar + 24);
    }
    __syncthreads();
    if (wid == 0) TCGEN05_DEALLOC(tmem, TCOLS);

#else
    // Naive correct fallback (never selected when sm_103a SASS is present)
    (void)smem_raw;
    const int MT = 128 * MH;
    for (int o = tid; o < MT * 256; o += 256) {
        const int mi = o >> 8;
        const int ni = o & 255;
        const float* a = p.A + (size_t)z * p.strideAz + (size_t)(bm * MT + mi) * p.lda;
        const float* b = p.B + (size_t)z * p.strideBz + (size_t)(bn * 256 + ni) * p.ldb;
        float acc = 0.f;
        for (int k = 0; k < p.K; k++) acc += a[k] * b[k];
        float v = acc * p.alpha;
        const int n0 = bn * 256 + ni;
        if (p.bias) v += p.bias[n0];
        if (ROUND) v = __uint_as_float(f2tf32(v));
        const int mg = bm * MT + mi;
        if (EPI == 1) {
            const int bb = mg >> 10, s = mg & 1023;
            const int h = n0 / F3, f = n0 - h * F3;
            g_qkv[(((size_t)(bb * Hn + h)) * Sn + s) * F3 + f] = v;
        } else {
            p.C[coff + (size_t)mg * p.ldc + n0] = v;
        }
    }
#endif
}

// Round-copy: dst = tf32_rna(src)
__global__ void __launch_bounds__(256) round_copy(const float* __restrict__ s,
                                                  float* __restrict__ d, int n4)
{
    int i = blockIdx.x * blockDim.x + threadIdx.x;
    if (i < n4) {
        float4 v = ((const float4*)s)[i];
        uint4 o;
        o.x = f2tf32(v.x); o.y = f2tf32(v.y); o.z = f2tf32(v.z); o.w = f2tf32(v.w);
        ((uint4*)d)[i] = o;
    }
}

// Transpose V slab of qkv: vT[bh, e, s] = qkv[bh, s, 2E + e] (already rounded)
__global__ void __launch_bounds__(256) transpose_v()
{
    __shared__ float tile[32][33];
    const int bh = blockIdx.z;
    const int s0 = blockIdx.x * 32;
    const int e0 = blockIdx.y * 32;
    const int tx = threadIdx.x;
    const int ty = threadIdx.y;
    const float* src = g_qkv + ((size_t)bh * Sn) * F3 + 2 * En;
    float* dst = g_vT + ((size_t)bh * En) * Sn;

    #pragma unroll
    for (int j = 0; j < 4; j++)
        tile[ty + 8 * j][tx] = src[(size_t)(s0 + ty + 8 * j) * F3 + e0 + tx];
    __syncthreads();
    #pragma unroll
    for (int j = 0; j < 4; j++)
        dst[(size_t)(e0 + ty + 8 * j) * Sn + s0 + tx] = tile[tx][ty + 8 * j];
}

// Softmax rows; output rounded to tf32 bits (AV GEMM input).
__global__ void __launch_bounds__(256) softmax_kernel(float* sc)
{
    float* row = sc + (size_t)blockIdx.x * Sn;
    const int tid = threadIdx.x;
    const int lane = tid & 31;
    const int wid = tid >> 5;
    __shared__ float red[8];

    float4 v = ((const float4*)row)[tid];
    float m = fmaxf(fmaxf(v.x, v.y), fmaxf(v.z, v.w));
    #pragma unroll
    for (int o = 16; o; o >>= 1) m = fmaxf(m, __shfl_xor_sync(~0u, m, o));
    if (lane == 0) red[wid] = m;
    __syncthreads();
    float bm = red[0];
    #pragma unroll
    for (int i = 1; i < 8; i++) bm = fmaxf(bm, red[i]);
    __syncthreads();

    float4 e;
    e.x = __expf(v.x - bm);
    e.y = __expf(v.y - bm);
    e.z = __expf(v.z - bm);
    e.w = __expf(v.w - bm);
    float s = e.x + e.y + e.z + e.w;
    #pragma unroll
    for (int o = 16; o; o >>= 1) s += __shfl_xor_sync(~0u, s, o);
    if (lane == 0) red[wid] = s;
    __syncthreads();
    float bs = red[0];
    #pragma unroll
    for (int i = 1; i < 8; i++) bs += red[i];
    const float rdiv = __frcp_rn(bs);

    uint4 o;
    o.x = f2tf32(e.x * rdiv);
    o.y = f2tf32(e.y * rdiv);
    o.z = f2tf32(e.z * rdiv);
    o.w = f2tf32(e.w * rdiv);
    ((uint4*)row)[tid] = o;
}

#define SMEM_MH2 (131072 + 1024)
#define SMEM_MH1 (98304 + 1024)

// Host-side tensormap builder via driver entry point (no -lcuda needed)
typedef CUresult (*PFN_encodeTM)(CUtensorMap*, CUtensorMapDataType, cuuint32_t, void*,
                                 const cuuint64_t*, const cuuint64_t*, const cuuint32_t*,
                                 const cuuint32_t*, CUtensorMapInterleave, CUtensorMapSwizzle,
                                 CUtensorMapL2promotion, CUtensorMapFloatOOBfill);

static void make_map(CUtensorMap* m, const void* base,
                     unsigned long long d0, unsigned long long d1, unsigned long long d2,
                     unsigned long long s1b, unsigned long long s2b,
                     unsigned int b0, unsigned int b1)
{
    void* fp = nullptr;
    cudaDriverEntryPointQueryResult st;
    cudaGetDriverEntryPoint("cuTensorMapEncodeTiled", &fp, cudaEnableDefault, &st);
    PFN_encodeTM enc = (PFN_encodeTM)fp;
    cuuint64_t dims[3] = {d0, d1, d2};
    cuuint64_t str[2]  = {s1b, s2b};
    cuuint32_t box[3]  = {b0, b1, 1};
    cuuint32_t es[3]   = {1, 1, 1};
    enc(m, CU_TENSOR_MAP_DATA_TYPE_FLOAT32, 3, (void*)base, dims, str, box, es,
        CU_TENSOR_MAP_INTERLEAVE_NONE, CU_TENSOR_MAP_SWIZZLE_128B,
        CU_TENSOR_MAP_L2_PROMOTION_L2_128B, CU_TENSOR_MAP_FLOAT_OOB_FILL_NONE);
}

extern "C" void kernel_launch(void* const* d_in, const int* in_sizes, int n_in,
                              void* d_out, int out_size)
{
    const float* x     = (const float*)d_in[0];  // [B,S,E]
    const float* qkv_w = (const float*)d_in[1];  // [H,3E,E]
    const float* qkv_b = (const float*)d_in[2];  // [H,3E]
    const float* out_w = (const float*)d_in[3];  // [E,H*E]
    const float* out_b = (const float*)d_in[4];  // [E]
    float* out = (float*)d_out;                  // [B,S,E]

    float *qkv, *scores, *vT, *concat, *xr, *wr, *owr;
    cudaGetSymbolAddress((void**)&qkv,    g_qkv);
    cudaGetSymbolAddress((void**)&scores, g_scores);
    cudaGetSymbolAddress((void**)&vT,     g_vT);
    cudaGetSymbolAddress((void**)&concat, g_concat);
    cudaGetSymbolAddress((void**)&xr,     g_xr);
    cudaGetSymbolAddress((void**)&wr,     g_wqkvr);
    cudaGetSymbolAddress((void**)&owr,    g_owr);

    cudaFuncSetAttribute(gemm_tma<2,1,1>, cudaFuncAttributeMaxDynamicSharedMemorySize, SMEM_MH2);
    cudaFuncSetAttribute(gemm_tma<2,0,0>, cudaFuncAttributeMaxDynamicSharedMemorySize, SMEM_MH2);
    cudaFuncSetAttribute(gemm_tma<2,0,1>, cudaFuncAttributeMaxDynamicSharedMemorySize, SMEM_MH2);
    cudaFuncSetAttribute(gemm_tma<1,0,0>, cudaFuncAttributeMaxDynamicSharedMemorySize, SMEM_MH1);

    // 0) Pre-round inputs to tf32 bits
    round_copy<<<(Bn*Sn*En/4 + 255)/256, 256>>>(x, xr, Bn*Sn*En/4);
    round_copy<<<(NQKV*En/4 + 255)/256, 256>>>(qkv_w, wr, NQKV*En/4);
    round_copy<<<(En*HE/4 + 255)/256, 256>>>(out_w, owr, En*HE/4);

    // Tensormaps (host-side, capture-safe)
    CUtensorMap mXA, mWB, mQA, mKB, mPA, mVB, mCA, mOB;
    make_map(&mXA, xr,      En, (unsigned long long)Bn*Sn, 1,
             (unsigned long long)En*4, (unsigned long long)Bn*Sn*En*4, 32, 256);
    make_map(&mWB, wr,      En, NQKV, 1,
             (unsigned long long)En*4, (unsigned long long)NQKV*En*4, 32, 256);
    make_map(&mQA, qkv,     En, Sn, Bn*Hn,
             (unsigned long long)F3*4, (unsigned long long)Sn*F3*4, 32, 256);
    make_map(&mKB, qkv+En,  En, Sn, Bn*Hn,
             (unsigned long long)F3*4, (unsigned long long)Sn*F3*4, 32, 256);
    make_map(&mPA, scores,  Sn, Sn, Bn*Hn,
             (unsigned long long)Sn*4, (unsigned long long)Sn*Sn*4, 32, 256);
    make_map(&mVB, vT,      Sn, En, Bn*Hn,
             (unsigned long long)Sn*4, (unsigned long long)En*Sn*4, 32, 256);
    make_map(&mCA, concat,  HE, (unsigned long long)Bn*Sn, 1,
             (unsigned long long)HE*4, (unsigned long long)Bn*Sn*HE*4, 32, 128);
    make_map(&mOB, owr,     HE, En, 1,
             (unsigned long long)HE*4, (unsigned long long)En*HE*4, 32, 256);

    // 1) QKV projection -> scatter [B,H,S,3E], +bias, rounded. 256x256 tiles.
    {
        GemmParams p = {};
        p.A = xr; p.B = wr; p.C = qkv;
        p.K = En; p.lda = En; p.ldb = En; p.ldc = 0;
        p.divH = 1; p.bias = qkv_b; p.alpha = 1.0f;
        gemm_tma<2,1,1><<<dim3(NQKV/256, (Bn*Sn)/256, 1), 256, SMEM_MH2>>>(mXA, mWB, p);
    }

    // 1b) Transpose V slab -> vT [B*H, E, S]
    transpose_v<<<dim3(Sn/32, En/32, Bn*Hn), dim3(32, 8)>>>();

    // 2) Scores: Q x K^T * scale. 256x256 tiles.
    {
        GemmParams p = {};
        p.A = qkv; p.B = qkv + En; p.C = scores;
        p.K = En; p.lda = F3; p.ldb = F3; p.ldc = Sn;
        p.strideAz = (long long)Sn*F3; p.strideBz = (long long)Sn*F3;
        p.strideCb = (long long)Sn*Sn; p.divH = 1;
        p.bias = nullptr; p.alpha = 0.036084391824351615f; // 1/sqrt(768)
        gemm_tma<2,0,0><<<dim3(Sn/256, Sn/256, Bn*Hn), 256, SMEM_MH2>>>(mQA, mKB, p);
    }

    // 3) Softmax rows (rounds output)
    softmax_kernel<<<Bn*Hn*Sn, 256>>>(scores);

    // 4) AV: P x vT^T -> concat, rounded. 256x256 tiles.
    {
        GemmParams p = {};
        p.A = scores; p.B = vT; p.C = concat;
        p.K = Sn; p.lda = Sn; p.ldb = Sn; p.ldc = HE;
        p.strideAz = (long long)Sn*Sn; p.strideBz = (long long)En*Sn;
        p.strideCb = (long long)Sn*Hn*En; p.strideCh = En; p.divH = Hn;
        p.bias = nullptr; p.alpha = 1.0f;
        gemm_tma<2,0,1><<<dim3(En/256, Sn/256, Bn*Hn), 256, SMEM_MH2>>>(mPA, mVB, p);
    }

    // 5) Output projection + bias -> out. 128x256 tiles (grid occupancy: 192 CTAs).
    {
        GemmParams p = {};
        p.A = concat; p.B = owr; p.C = out;
        p.K = HE; p.lda = HE; p.ldb = HE; p.ldc = En;
        p.divH = 1; p.bias = out_b; p.alpha = 1.0f;
        gemm_tma<1,0,0><<<dim3(En/256, (Bn*Sn)/128, 1), 256, SMEM_MH1>>>(mCA, mOB, p);
    }
}

// round 11
// speedup vs baseline: 1.0366x; 1.0366x over previous
#include <cuda_runtime.h>
#include <cuda.h>
#include <stdint.h>

// Problem constants
#define Bn 8
#define Sn 1024
#define En 768
#define Hn 12
#define F3 2304          // 3*E
#define NQKV 27648       // H*3E
#define HE 9216          // H*E

// Scratch (allocation-free: __device__ globals)
__device__ float g_qkv[(size_t)Bn * Hn * Sn * F3];     // [B,H,S,3E] (tf32-rounded)
__device__ float g_scores[(size_t)Bn * Hn * Sn * Sn];  // [B*H,S,S]
__device__ float g_vT[(size_t)Bn * Hn * En * Sn];      // [B*H,E,S]  (tf32-rounded)
__device__ float g_concat[(size_t)Bn * Sn * Hn * En];  // [B,S,H,E]  (tf32-rounded)
__device__ float g_xr[(size_t)Bn * Sn * En];           // rounded x
__device__ float g_wqkvr[(size_t)NQKV * En];           // rounded qkv_w
__device__ float g_owr[(size_t)En * HE];               // rounded out_w

struct GemmParams {
    const float* A;   // [M,K] K-major (fallback only)
    const float* B;   // [N,K] K-major (fallback only)
    float* C;
    int K;
    int lda, ldb, ldc;
    long long strideAz, strideBz;
    long long strideCb, strideCh;
    int divH;
    const float* bias;
    float alpha;
};

__device__ __forceinline__ uint32_t f2tf32(float x) {
    uint32_t r;
    asm("cvt.rna.tf32.f32 %0, %1;" : "=r"(r) : "f"(x));
    return r;
}

__device__ __forceinline__ uint32_t smem_u32_g(const void* p) {
    uint32_t a;
    asm("{ .reg .u64 t; cvta.to.shared.u64 t, %1; cvt.u32.u64 %0, t; }"
        : "=r"(a) : "l"(p));
    return a;
}

#if defined(__CUDA_ARCH_FEAT_SM103_ALL)
// ---------- sm_103a-only helpers ----------
__device__ __forceinline__ uint32_t elect_one() {
    uint32_t p;
    asm volatile(
        "{\n\t.reg .pred p;\n\telect.sync _|p, 0xFFFFFFFF;\n\t"
        "selp.b32 %0, 1, 0, p;\n\t}" : "=r"(p));
    return p;
}

#define TCGEN05_ALLOC(a, n) \
    asm volatile("tcgen05.alloc.cta_group::1.sync.aligned.shared::cta.b32 [%0], %1;" \
                 :: "r"(a), "r"(n) : "memory")
#define TCGEN05_DEALLOC(t, n) \
    asm volatile("tcgen05.dealloc.cta_group::1.sync.aligned.b32 %0, %1;" :: "r"(t), "r"(n))
#define TCGEN05_RELINQ() \
    asm volatile("tcgen05.relinquish_alloc_permit.cta_group::1.sync.aligned;")
#define TCGEN05_COMMIT(m) \
    asm volatile("tcgen05.commit.cta_group::1.mbarrier::arrive::one.shared::cluster.b64 [%0];" \
                 :: "r"(m) : "memory")
#define MBARRIER_INIT(m, c) \
    asm volatile("mbarrier.init.shared.b64 [%0], %1;" :: "r"(m), "r"(c) : "memory")
#define MBARRIER_INVAL(m) \
    asm volatile("mbarrier.inval.shared.b64 [%0];" :: "r"(m) : "memory")
#define MBARRIER_EXPECT_TX(m, b) \
    asm volatile("mbarrier.arrive.expect_tx.shared.b64 _, [%0], %1;" \
                 :: "r"(m), "r"(b) : "memory")
#define TCGEN05_FENCE_AFTER()  asm volatile("tcgen05.fence::after_thread_sync;" ::: "memory")
#define TCGEN05_FENCE_BEFORE() asm volatile("tcgen05.fence::before_thread_sync;" ::: "memory")
#define TCGEN05_WAIT_LD()      asm volatile("tcgen05.wait::ld.sync.aligned;" ::: "memory")
#define FENCE_ASYNC()          asm volatile("fence.proxy.async.shared::cta;" ::: "memory")

#define TMA3D(sm, mapp, cx, cy, cz, mb) \
    asm volatile( \
        "cp.async.bulk.tensor.3d.shared::cta.global.tile.mbarrier::complete_tx::bytes " \
        "[%0], [%1, {%2, %3, %4}], [%5];" \
        :: "r"(sm), "l"(mapp), "r"(cx), "r"(cy), "r"(cz), "r"(mb) : "memory")

#define MBARRIER_WAIT_PARITY(mbar_smem_addr, phase_parity) do { \
    uint32_t _mbar = (uint32_t)(mbar_smem_addr); \
    uint32_t _parity = (uint32_t)(phase_parity); \
    uint32_t _done; \
    asm volatile( \
        "{\n\t.reg .pred p;\n\t" \
        "mbarrier.try_wait.parity.acquire.cta.shared::cta.b64 p, [%1], %2;\n\t" \
        "selp.b32 %0, 1, 0, p;\n\t}" \
        : "=r"(_done) : "r"(_mbar), "r"(_parity) : "memory"); \
    if (!_done) { \
        asm volatile( \
            "{\n\t.reg .pred P1;\n\t" \
            "WAIT_LOOP_%=:\n\t" \
            "mbarrier.try_wait.parity.acquire.cta.shared::cta.b64 P1, [%0], %1, 0x989680;\n\t" \
            "@P1 bra.uni WAIT_DONE_%=;\n\t" \
            "bra.uni WAIT_LOOP_%=;\n\t" \
            "WAIT_DONE_%=:\n\t}" \
            :: "r"(_mbar), "r"(_parity) : "memory"); \
    } \
} while (0)

#define TCGEN05_LD_32X32B_X32(r, tmem_addr) \
    asm volatile( \
        "tcgen05.ld.sync.aligned.32x32b.x32.b32 " \
        "{%0, %1, %2, %3, %4, %5, %6, %7, " \
        " %8, %9, %10, %11, %12, %13, %14, %15, " \
        " %16, %17, %18, %19, %20, %21, %22, %23, " \
        " %24, %25, %26, %27, %28, %29, %30, %31}, [%32];" \
        : "=r"((r)[0]),  "=r"((r)[1]),  "=r"((r)[2]),  "=r"((r)[3]), \
          "=r"((r)[4]),  "=r"((r)[5]),  "=r"((r)[6]),  "=r"((r)[7]), \
          "=r"((r)[8]),  "=r"((r)[9]),  "=r"((r)[10]), "=r"((r)[11]), \
          "=r"((r)[12]), "=r"((r)[13]), "=r"((r)[14]), "=r"((r)[15]), \
          "=r"((r)[16]), "=r"((r)[17]), "=r"((r)[18]), "=r"((r)[19]), \
          "=r"((r)[20]), "=r"((r)[21]), "=r"((r)[22]), "=r"((r)[23]), \
          "=r"((r)[24]), "=r"((r)[25]), "=r"((r)[26]), "=r"((r)[27]), \
          "=r"((r)[28]), "=r"((r)[29]), "=r"((r)[30]), "=r"((r)[31]) \
        : "r"(tmem_addr))

// SW128 K-major SMEM descriptor (128B rows): layout=SW128, version=1, SBO=64, LBO=1
static __device__ __forceinline__ uint64_t mk_desc(uint32_t addr) {
    const uint64_t base = (2ULL << 61) | (1ULL << 46) | (64ULL << 32) | (1ULL << 16);
    return base | ((uint64_t)(addr >> 4) & 0x3FFF);
}

// idesc kind::tf32: dtype F32=1 @bit4, atype=btype=TF32=2 @bits7/10,
// N/8 @bit17, M/16 @bit24   (M=128, N=256)
#define IDESC_TF32 ((1u << 4) | (2u << 7) | (2u << 10) | (32u << 17) | (8u << 24))

__device__ __forceinline__ void mma_tf32_ss(uint32_t d_tmem, uint64_t ad, uint64_t bd,
                                            uint32_t en) {
    asm volatile(
        "{\n\t.reg .pred pq;\n\tsetp.ne.u32 pq, %5, 0;\n\t"
        "tcgen05.mma.cta_group::1.kind::tf32 [%0], %1, %2, %3, {%4, %4, %4, %4}, pq;\n\t}"
        :: "r"(d_tmem), "l"(ad), "l"(bd), "r"(IDESC_TF32), "r"(0u), "r"(en)
        : "memory");
}
#endif  // __CUDA_ARCH_FEAT_SM103_ALL

// ---------- GEMM: A[M,K] x B[N,K]^T, tile (128*MH)x256, 256 threads ----------
// sm_103a: TMA-fed NS-stage ring tcgen05 SS pipeline. MH=2 -> 256-row tiles,
// two M=128 MMAs per chunk into TMEM cols [0,256) and [256,512).
// EPI: 0 = plain C write, 1 = QKV scatter. ROUND: round stored values to tf32.
template <int MH, int NS, int EPI, int ROUND>
__global__ void __launch_bounds__(256) gemm_tma(
    const __grid_constant__ CUtensorMap mA,
    const __grid_constant__ CUtensorMap mB,
    GemmParams p)
{
    extern __shared__ __align__(16) float smem_raw[];
    const int tid = threadIdx.x;
    const int lane = tid & 31;
    const int wid = tid >> 5;
    const int bn = blockIdx.x, bm = blockIdx.y, z = blockIdx.z;
    const size_t coff = (size_t)(z / p.divH) * p.strideCb +
                        (size_t)(z % p.divH) * p.strideCh;

#if defined(__CUDA_ARCH_FEAT_SM103_ALL)
    __shared__ uint32_t s_tmem;
    __shared__ __align__(8) unsigned long long s_mbar[2 * NS];  // full[NS], done[NS]

    const uint32_t raw_u  = smem_u32_g(smem_raw);
    const uint32_t smem_u = (raw_u + 1023u) & ~1023u;   // SW128 atom alignment
    const uint32_t mbar   = smem_u32_g(s_mbar);         // full[s]=mbar+8s, done[s]=mbar+8(NS+s)

    constexpr uint32_t ASZ = MH * 16384u;       // A stage bytes
    constexpr uint32_t SZ  = ASZ + 32768u;      // stage bytes (A+B)
    constexpr uint32_t TCOLS = MH * 256u;

    if (wid == 0) { TCGEN05_ALLOC(smem_u32_g(&s_tmem), TCOLS); TCGEN05_RELINQ(); }
    if (tid == 0) {
        #pragma unroll
        for (int s = 0; s < 2 * NS; s++) MBARRIER_INIT(mbar + 8 * s, 1);
        FENCE_ASYNC();
    }
    __syncthreads();
    const uint32_t tmem = s_tmem;

    const int nIter = p.K >> 5;   // 24 / 32 / 288

    if (wid == 0) {
        if (elect_one()) {
            const CUtensorMap* pA = &mA;
            const CUtensorMap* pB = &mB;
            const int m0 = bm * (128 * MH);
            const int n0 = bn * 256;
            int phf[NS], phd[NS];
            #pragma unroll
            for (int s = 0; s < NS; s++) { phf[s] = 0; phd[s] = 0; }

            // Prologue: fill the ring
            const int pre = (nIter < NS) ? nIter : NS;
            for (int s = 0; s < pre; s++) {
                MBARRIER_EXPECT_TX(mbar + 8 * s, SZ);
                TMA3D(smem_u + s * SZ, pA, s * 32, m0, z, mbar + 8 * s);
                TMA3D(smem_u + s * SZ + ASZ, pB, s * 32, n0, z, mbar + 8 * s);
            }

            for (int kt = 0; kt < nIter; kt++) {
                const int b = kt % NS;
                MBARRIER_WAIT_PARITY(mbar + 8 * b, phf[b]); phf[b] ^= 1;
                const uint32_t oa = smem_u + b * SZ;
                const uint64_t bd = mk_desc(oa + ASZ);
                #pragma unroll
                for (int ks = 0; ks < 4; ks++) {
                    #pragma unroll
                    for (int mh = 0; mh < MH; mh++) {
                        const uint64_t ad = mk_desc(oa + mh * 16384u);
                        mma_tf32_ss(tmem + mh * 256, ad + ks * 2, bd + ks * 2,
                                    (kt > 0 || ks > 0) ? 1u : 0u);
                    }
                }
                TCGEN05_COMMIT(mbar + 8 * (NS + b));

                const int next = kt + NS;
                if (next < nIter) {
                    // MMA(kt) must be done reading buf b before refill
                    MBARRIER_WAIT_PARITY(mbar + 8 * (NS + b), phd[b]); phd[b] ^= 1;
                    MBARRIER_EXPECT_TX(mbar + 8 * b, SZ);
                    TMA3D(oa, pA, next * 32, m0, z, mbar + 8 * b);
                    TMA3D(oa + ASZ, pB, next * 32, n0, z, mbar + 8 * b);
                }
            }
            // Drain remaining done-commits
            const int tail = (nIter < NS) ? nIter : NS;
            for (int kt = nIter - tail; kt < nIter; kt++) {
                const int b = kt % NS;
                MBARRIER_WAIT_PARITY(mbar + 8 * (NS + b), phd[b]); phd[b] ^= 1;
            }
        }
    }
    __syncthreads();
    TCGEN05_FENCE_AFTER();

    // Epilogue.
    // MH=2: warps 0-3 -> M-half 0 (TMEM cols 0-255), warps 4-7 -> M-half 1
    //       (cols 256-511). Each warp: 8 x 32-col slices covering n [0,256).
    // MH=1: warps 0-3 -> cols 0-127, warps 4-7 -> cols 128-255 (4 slices).
    const int nslice = (MH == 2) ? 8 : 4;
    const int m = bm * (128 * MH) +
                  ((MH == 2) ? (wid >> 2) * 128 : 0) + (wid & 3) * 32 + lane;
    const uint32_t tbase = tmem + ((MH == 2) ? (uint32_t)(wid >> 2) * 256u
                                             : (uint32_t)(wid >> 2) * 128u);
    const int nbase = bn * 256 + ((MH == 2) ? 0 : (wid >> 2) * 128);

    for (int i = 0; i < nslice; i++) {
        uint32_t r[32];
        TCGEN05_LD_32X32B_X32(r, tbase + i * 32);
        TCGEN05_WAIT_LD();
        const int n0 = nbase + i * 32;
        float* dst;
        if (EPI == 1) {
            const int b = m >> 10, s = m & 1023;
            const int h = n0 / F3, f = n0 - h * F3;
            dst = &g_qkv[(((size_t)(b * Hn + h)) * Sn + s) * F3 + f];
        } else {
            dst = &p.C[coff + (size_t)m * p.ldc + n0];
        }
        #pragma unroll
        for (int j = 0; j < 32; j += 4) {
            float4 v;
            v.x = __uint_as_float(r[j + 0]) * p.alpha;
            v.y = __uint_as_float(r[j + 1]) * p.alpha;
            v.z = __uint_as_float(r[j + 2]) * p.alpha;
            v.w = __uint_as_float(r[j + 3]) * p.alpha;
            if (p.bias) {
                float4 bb = *(const float4*)&p.bias[n0 + j];
                v.x += bb.x; v.y += bb.y; v.z += bb.z; v.w += bb.w;
            }
            if (ROUND) {
                v.x = __uint_as_float(f2tf32(v.x));
                v.y = __uint_as_float(f2tf32(v.y));
                v.z = __uint_as_float(f2tf32(v.z));
                v.w = __uint_as_float(f2tf32(v.w));
            }
            *(float4*)&dst[j] = v;
        }
    }
    TCGEN05_FENCE_BEFORE();

    __syncthreads();
    if (tid == 0) {
        #pragma unroll
        for (int s = 0; s < 2 * NS; s++) MBARRIER_INVAL(mbar + 8 * s);
    }
    __syncthreads();
    if (wid == 0) TCGEN05_DEALLOC(tmem, TCOLS);

#else
    // Naive correct fallback (never selected when sm_103a SASS is present)
    (void)smem_raw;
    const int MT = 128 * MH;
    for (int o = tid; o < MT * 256; o += 256) {
        const int mi = o >> 8;
        const int ni = o & 255;
        const float* a = p.A + (size_t)z * p.strideAz + (size_t)(bm * MT + mi) * p.lda;
        const float* b = p.B + (size_t)z * p.strideBz + (size_t)(bn * 256 + ni) * p.ldb;
        float acc = 0.f;
        for (int k = 0; k < p.K; k++) acc += a[k] * b[k];
        float v = acc * p.alpha;
        const int n0 = bn * 256 + ni;
        if (p.bias) v += p.bias[n0];
        if (ROUND) v = __uint_as_float(f2tf32(v));
        const int mg = bm * MT + mi;
        if (EPI == 1) {
            const int bb = mg >> 10, s = mg & 1023;
            const int h = n0 / F3, f = n0 - h * F3;
            g_qkv[(((size_t)(bb * Hn + h)) * Sn + s) * F3 + f] = v;
        } else {
            p.C[coff + (size_t)mg * p.ldc + n0] = v;
        }
    }
#endif
}

// Round-copy: dst = tf32_rna(src)
__global__ void __launch_bounds__(256) round_copy(const float* __restrict__ s,
                                                  float* __restrict__ d, int n4)
{
    int i = blockIdx.x * blockDim.x + threadIdx.x;
    if (i < n4) {
        float4 v = ((const float4*)s)[i];
        uint4 o;
        o.x = f2tf32(v.x); o.y = f2tf32(v.y); o.z = f2tf32(v.z); o.w = f2tf32(v.w);
        ((uint4*)d)[i] = o;
    }
}

// Transpose V slab of qkv: vT[bh, e, s] = qkv[bh, s, 2E + e] (already rounded)
__global__ void __launch_bounds__(256) transpose_v()
{
    __shared__ float tile[32][33];
    const int bh = blockIdx.z;
    const int s0 = blockIdx.x * 32;
    const int e0 = blockIdx.y * 32;
    const int tx = threadIdx.x;
    const int ty = threadIdx.y;
    const float* src = g_qkv + ((size_t)bh * Sn) * F3 + 2 * En;
    float* dst = g_vT + ((size_t)bh * En) * Sn;

    #pragma unroll
    for (int j = 0; j < 4; j++)
        tile[ty + 8 * j][tx] = src[(size_t)(s0 + ty + 8 * j) * F3 + e0 + tx];
    __syncthreads();
    #pragma unroll
    for (int j = 0; j < 4; j++)
        dst[(size_t)(e0 + ty + 8 * j) * Sn + s0 + tx] = tile[tx][ty + 8 * j];
}

// Softmax rows; output rounded to tf32 bits (AV GEMM input).
__global__ void __launch_bounds__(256) softmax_kernel(float* sc)
{
    float* row = sc + (size_t)blockIdx.x * Sn;
    const int tid = threadIdx.x;
    const int lane = tid & 31;
    const int wid = tid >> 5;
    __shared__ float red[8];

    float4 v = ((const float4*)row)[tid];
    float m = fmaxf(fmaxf(v.x, v.y), fmaxf(v.z, v.w));
    #pragma unroll
    for (int o = 16; o; o >>= 1) m = fmaxf(m, __shfl_xor_sync(~0u, m, o));
    if (lane == 0) red[wid] = m;
    __syncthreads();
    float bm = red[0];
    #pragma unroll
    for (int i = 1; i < 8; i++) bm = fmaxf(bm, red[i]);
    __syncthreads();

    float4 e;
    e.x = __expf(v.x - bm);
    e.y = __expf(v.y - bm);
    e.z = __expf(v.z - bm);
    e.w = __expf(v.w - bm);
    float s = e.x + e.y + e.z + e.w;
    #pragma unroll
    for (int o = 16; o; o >>= 1) s += __shfl_xor_sync(~0u, s, o);
    if (lane == 0) red[wid] = s;
    __syncthreads();
    float bs = red[0];
    #pragma unroll
    for (int i = 1; i < 8; i++) bs += red[i];
    const float rdiv = __frcp_rn(bs);

    uint4 o;
    o.x = f2tf32(e.x * rdiv);
    o.y = f2tf32(e.y * rdiv);
    o.z = f2tf32(e.z * rdiv);
    o.w = f2tf32(e.w * rdiv);
    ((uint4*)row)[tid] = o;
}

#define SMEM_RING (196608 + 1024)   // 3x64KB (MH2) or 4x48KB (MH1) + align slack

// Host-side tensormap builder via driver entry point (no -lcuda needed)
typedef CUresult (*PFN_encodeTM)(CUtensorMap*, CUtensorMapDataType, cuuint32_t, void*,
                                 const cuuint64_t*, const cuuint64_t*, const cuuint32_t*,
                                 const cuuint32_t*, CUtensorMapInterleave, CUtensorMapSwizzle,
                                 CUtensorMapL2promotion, CUtensorMapFloatOOBfill);

static void make_map(CUtensorMap* m, const void* base,
                     unsigned long long d0, unsigned long long d1, unsigned long long d2,
                     unsigned long long s1b, unsigned long long s2b,
                     unsigned int b0, unsigned int b1)
{
    void* fp = nullptr;
    cudaDriverEntryPointQueryResult st;
    cudaGetDriverEntryPoint("cuTensorMapEncodeTiled", &fp, cudaEnableDefault, &st);
    PFN_encodeTM enc = (PFN_encodeTM)fp;
    cuuint64_t dims[3] = {d0, d1, d2};
    cuuint64_t str[2]  = {s1b, s2b};
    cuuint32_t box[3]  = {b0, b1, 1};
    cuuint32_t es[3]   = {1, 1, 1};
    enc(m, CU_TENSOR_MAP_DATA_TYPE_FLOAT32, 3, (void*)base, dims, str, box, es,
        CU_TENSOR_MAP_INTERLEAVE_NONE, CU_TENSOR_MAP_SWIZZLE_128B,
        CU_TENSOR_MAP_L2_PROMOTION_L2_128B, CU_TENSOR_MAP_FLOAT_OOB_FILL_NONE);
}

extern "C" void kernel_launch(void* const* d_in, const int* in_sizes, int n_in,
                              void* d_out, int out_size)
{
    const float* x     = (const float*)d_in[0];  // [B,S,E]
    const float* qkv_w = (const float*)d_in[1];  // [H,3E,E]
    const float* qkv_b = (const float*)d_in[2];  // [H,3E]
    const float* out_w = (const float*)d_in[3];  // [E,H*E]
    const float* out_b = (const float*)d_in[4];  // [E]
    float* out = (float*)d_out;                  // [B,S,E]

    float *qkv, *scores, *vT, *concat, *xr, *wr, *owr;
    cudaGetSymbolAddress((void**)&qkv,    g_qkv);
    cudaGetSymbolAddress((void**)&scores, g_scores);
    cudaGetSymbolAddress((void**)&vT,     g_vT);
    cudaGetSymbolAddress((void**)&concat, g_concat);
    cudaGetSymbolAddress((void**)&xr,     g_xr);
    cudaGetSymbolAddress((void**)&wr,     g_wqkvr);
    cudaGetSymbolAddress((void**)&owr,    g_owr);

    cudaFuncSetAttribute(gemm_tma<2,3,1,1>, cudaFuncAttributeMaxDynamicSharedMemorySize, SMEM_RING);
    cudaFuncSetAttribute(gemm_tma<2,3,0,0>, cudaFuncAttributeMaxDynamicSharedMemorySize, SMEM_RING);
    cudaFuncSetAttribute(gemm_tma<2,3,0,1>, cudaFuncAttributeMaxDynamicSharedMemorySize, SMEM_RING);
    cudaFuncSetAttribute(gemm_tma<1,4,0,0>, cudaFuncAttributeMaxDynamicSharedMemorySize, SMEM_RING);

    // 0) Pre-round inputs to tf32 bits
    round_copy<<<(Bn*Sn*En/4 + 255)/256, 256>>>(x, xr, Bn*Sn*En/4);
    round_copy<<<(NQKV*En/4 + 255)/256, 256>>>(qkv_w, wr, NQKV*En/4);
    round_copy<<<(En*HE/4 + 255)/256, 256>>>(out_w, owr, En*HE/4);

    // Tensormaps (host-side, capture-safe)
    CUtensorMap mXA, mWB, mQA, mKB, mPA, mVB, mCA, mOB;
    make_map(&mXA, xr,      En, (unsigned long long)Bn*Sn, 1,
             (unsigned long long)En*4, (unsigned long long)Bn*Sn*En*4, 32, 256);
    make_map(&mWB, wr,      En, NQKV, 1,
             (unsigned long long)En*4, (unsigned long long)NQKV*En*4, 32, 256);
    make_map(&mQA, qkv,     En, Sn, Bn*Hn,
             (unsigned long long)F3*4, (unsigned long long)Sn*F3*4, 32, 256);
    make_map(&mKB, qkv+En,  En, Sn, Bn*Hn,
             (unsigned long long)F3*4, (unsigned long long)Sn*F3*4, 32, 256);
    make_map(&mPA, scores,  Sn, Sn, Bn*Hn,
             (unsigned long long)Sn*4, (unsigned long long)Sn*Sn*4, 32, 256);
    make_map(&mVB, vT,      Sn, En, Bn*Hn,
             (unsigned long long)Sn*4, (unsigned long long)En*Sn*4, 32, 256);
    make_map(&mCA, concat,  HE, (unsigned long long)Bn*Sn, 1,
             (unsigned long long)HE*4, (unsigned long long)Bn*Sn*HE*4, 32, 128);
    make_map(&mOB, owr,     HE, En, 1,
             (unsigned long long)HE*4, (unsigned long long)En*HE*4, 32, 256);

    // 1) QKV projection -> scatter [B,H,S,3E], +bias, rounded. 256x256, 3-stage.
    {
        GemmParams p = {};
        p.A = xr; p.B = wr; p.C = qkv;
        p.K = En; p.lda = En; p.ldb = En; p.ldc = 0;
        p.divH = 1; p.bias = qkv_b; p.alpha = 1.0f;
        gemm_tma<2,3,1,1><<<dim3(NQKV/256, (Bn*Sn)/256, 1), 256, SMEM_RING>>>(mXA, mWB, p);
    }

    // 1b) Transpose V slab -> vT [B*H, E, S]
    transpose_v<<<dim3(Sn/32, En/32, Bn*Hn), dim3(32, 8)>>>();

    // 2) Scores: Q x K^T * scale. 256x256, 3-stage.
    {
        GemmParams p = {};
        p.A = qkv; p.B = qkv + En; p.C = scores;
        p.K = En; p.lda = F3; p.ldb = F3; p.ldc = Sn;
        p.strideAz = (long long)Sn*F3; p.strideBz = (long long)Sn*F3;
        p.strideCb = (long long)Sn*Sn; p.divH = 1;
        p.bias = nullptr; p.alpha = 0.036084391824351615f; // 1/sqrt(768)
        gemm_tma<2,3,0,0><<<dim3(Sn/256, Sn/256, Bn*Hn), 256, SMEM_RING>>>(mQA, mKB, p);
    }

    // 3) Softmax rows (rounds output)
    softmax_kernel<<<Bn*Hn*Sn, 256>>>(scores);

    // 4) AV: P x vT^T -> concat, rounded. 256x256, 3-stage.
    {
        GemmParams p = {};
        p.A = scores; p.B = vT; p.C = concat;
        p.K = Sn; p.lda = Sn; p.ldb = Sn; p.ldc = HE;
        p.strideAz = (long long)Sn*Sn; p.strideBz = (long long)En*Sn;
        p.strideCb = (long long)Sn*Hn*En; p.strideCh = En; p.divH = Hn;
        p.bias = nullptr; p.alpha = 1.0f;
        gemm_tma<2,3,0,1><<<dim3(En/256, Sn/256, Bn*Hn), 256, SMEM_RING>>>(mPA, mVB, p);
    }

    // 5) Output projection + bias -> out. 128x256, 4-stage (K=9216: deep loop).
    {
        GemmParams p = {};
        p.A = concat; p.B = owr; p.C = out;
        p.K = HE; p.lda = HE; p.ldb = HE; p.ldc = En;
        p.divH = 1; p.bias = out_b; p.alpha = 1.0f;
        gemm_tma<1,4,0,0><<<dim3(En/256, (Bn*Sn)/128, 1), 256, SMEM_RING>>>(mCA, mOB, p);
    }
}

// round 12
// speedup vs baseline: 1.0423x; 1.0054x over previous
#include <cuda_runtime.h>
#include <cuda.h>
#include <stdint.h>

// Problem constants
#define Bn 8
#define Sn 1024
#define En 768
#define Hn 12
#define F3 2304          // 3*E
#define NQKV 27648       // H*3E
#define HE 9216          // H*E

// Scratch (allocation-free: __device__ globals)
__device__ float g_qkv[(size_t)Bn * Hn * Sn * F3];     // [B,H,S,3E] (tf32-rounded)
__device__ float g_scores[(size_t)Bn * Hn * Sn * Sn];  // [B*H,S,S]
__device__ float g_vT[(size_t)Bn * Hn * En * Sn];      // [B*H,E,S]  (tf32-rounded)
__device__ float g_concat[(size_t)Bn * Sn * Hn * En];  // [B,S,H,E]  (tf32-rounded)
__device__ float g_xr[(size_t)Bn * Sn * En];           // rounded x
__device__ float g_wqkvr[(size_t)NQKV * En];           // rounded qkv_w
__device__ float g_owr[(size_t)En * HE];               // rounded out_w

struct GemmParams {
    const float* A;   // [M,K] K-major (fallback only)
    const float* B;   // [N,K] K-major (fallback only)
    float* C;
    int K;
    int lda, ldb, ldc;
    long long strideAz, strideBz;
    long long strideCb, strideCh;
    int divH;
    const float* bias;
    float alpha;
};

__device__ __forceinline__ uint32_t f2tf32(float x) {
    uint32_t r;
    asm("cvt.rna.tf32.f32 %0, %1;" : "=r"(r) : "f"(x));
    return r;
}

__device__ __forceinline__ uint32_t smem_u32_g(const void* p) {
    uint32_t a;
    asm("{ .reg .u64 t; cvta.to.shared.u64 t, %1; cvt.u32.u64 %0, t; }"
        : "=r"(a) : "l"(p));
    return a;
}

#if defined(__CUDA_ARCH_FEAT_SM103_ALL)
// ---------- sm_103a-only helpers ----------
__device__ __forceinline__ uint32_t elect_one() {
    uint32_t p;
    asm volatile(
        "{\n\t.reg .pred p;\n\telect.sync _|p, 0xFFFFFFFF;\n\t"
        "selp.b32 %0, 1, 0, p;\n\t}" : "=r"(p));
    return p;
}

#define TCGEN05_ALLOC(a, n) \
    asm volatile("tcgen05.alloc.cta_group::1.sync.aligned.shared::cta.b32 [%0], %1;" \
                 :: "r"(a), "r"(n) : "memory")
#define TCGEN05_DEALLOC(t, n) \
    asm volatile("tcgen05.dealloc.cta_group::1.sync.aligned.b32 %0, %1;" :: "r"(t), "r"(n))
#define TCGEN05_RELINQ() \
    asm volatile("tcgen05.relinquish_alloc_permit.cta_group::1.sync.aligned;")
#define TCGEN05_COMMIT(m) \
    asm volatile("tcgen05.commit.cta_group::1.mbarrier::arrive::one.shared::cluster.b64 [%0];" \
                 :: "r"(m) : "memory")
#define MBARRIER_INIT(m, c) \
    asm volatile("mbarrier.init.shared.b64 [%0], %1;" :: "r"(m), "r"(c) : "memory")
#define MBARRIER_INVAL(m) \
    asm volatile("mbarrier.inval.shared.b64 [%0];" :: "r"(m) : "memory")
#define MBARRIER_EXPECT_TX(m, b) \
    asm volatile("mbarrier.arrive.expect_tx.shared.b64 _, [%0], %1;" \
                 :: "r"(m), "r"(b) : "memory")
#define TCGEN05_FENCE_AFTER()  asm volatile("tcgen05.fence::after_thread_sync;" ::: "memory")
#define TCGEN05_FENCE_BEFORE() asm volatile("tcgen05.fence::before_thread_sync;" ::: "memory")
#define TCGEN05_WAIT_LD()      asm volatile("tcgen05.wait::ld.sync.aligned;" ::: "memory")
#define FENCE_ASYNC()          asm volatile("fence.proxy.async.shared::cta;" ::: "memory")

#define TMA3D(sm, mapp, cx, cy, cz, mb) \
    asm volatile( \
        "cp.async.bulk.tensor.3d.shared::cta.global.tile.mbarrier::complete_tx::bytes " \
        "[%0], [%1, {%2, %3, %4}], [%5];" \
        :: "r"(sm), "l"(mapp), "r"(cx), "r"(cy), "r"(cz), "r"(mb) : "memory")

#define MBARRIER_WAIT_PARITY(mbar_smem_addr, phase_parity) do { \
    uint32_t _mbar = (uint32_t)(mbar_smem_addr); \
    uint32_t _parity = (uint32_t)(phase_parity); \
    uint32_t _done; \
    asm volatile( \
        "{\n\t.reg .pred p;\n\t" \
        "mbarrier.try_wait.parity.acquire.cta.shared::cta.b64 p, [%1], %2;\n\t" \
        "selp.b32 %0, 1, 0, p;\n\t}" \
        : "=r"(_done) : "r"(_mbar), "r"(_parity) : "memory"); \
    if (!_done) { \
        asm volatile( \
            "{\n\t.reg .pred P1;\n\t" \
            "WAIT_LOOP_%=:\n\t" \
            "mbarrier.try_wait.parity.acquire.cta.shared::cta.b64 P1, [%0], %1, 0x989680;\n\t" \
            "@P1 bra.uni WAIT_DONE_%=;\n\t" \
            "bra.uni WAIT_LOOP_%=;\n\t" \
            "WAIT_DONE_%=:\n\t}" \
            :: "r"(_mbar), "r"(_parity) : "memory"); \
    } \
} while (0)

#define TCGEN05_LD_32X32B_X32(r, tmem_addr) \
    asm volatile( \
        "tcgen05.ld.sync.aligned.32x32b.x32.b32 " \
        "{%0, %1, %2, %3, %4, %5, %6, %7, " \
        " %8, %9, %10, %11, %12, %13, %14, %15, " \
        " %16, %17, %18, %19, %20, %21, %22, %23, " \
        " %24, %25, %26, %27, %28, %29, %30, %31}, [%32];" \
        : "=r"((r)[0]),  "=r"((r)[1]),  "=r"((r)[2]),  "=r"((r)[3]), \
          "=r"((r)[4]),  "=r"((r)[5]),  "=r"((r)[6]),  "=r"((r)[7]), \
          "=r"((r)[8]),  "=r"((r)[9]),  "=r"((r)[10]), "=r"((r)[11]), \
          "=r"((r)[12]), "=r"((r)[13]), "=r"((r)[14]), "=r"((r)[15]), \
          "=r"((r)[16]), "=r"((r)[17]), "=r"((r)[18]), "=r"((r)[19]), \
          "=r"((r)[20]), "=r"((r)[21]), "=r"((r)[22]), "=r"((r)[23]), \
          "=r"((r)[24]), "=r"((r)[25]), "=r"((r)[26]), "=r"((r)[27]), \
          "=r"((r)[28]), "=r"((r)[29]), "=r"((r)[30]), "=r"((r)[31]) \
        : "r"(tmem_addr))

// SW128 K-major SMEM descriptor (128B rows): layout=SW128, version=1, SBO=64, LBO=1
static __device__ __forceinline__ uint64_t mk_desc(uint32_t addr) {
    const uint64_t base = (2ULL << 61) | (1ULL << 46) | (64ULL << 32) | (1ULL << 16);
    return base | ((uint64_t)(addr >> 4) & 0x3FFF);
}

// idesc kind::tf32: dtype F32=1 @bit4, atype=btype=TF32=2 @bits7/10,
// N/8 @bit17, M/16 @bit24   (M=128, N=256)
#define IDESC_TF32 ((1u << 4) | (2u << 7) | (2u << 10) | (32u << 17) | (8u << 24))

__device__ __forceinline__ void mma_tf32_ss(uint32_t d_tmem, uint64_t ad, uint64_t bd,
                                            uint32_t en) {
    asm volatile(
        "{\n\t.reg .pred pq;\n\tsetp.ne.u32 pq, %5, 0;\n\t"
        "tcgen05.mma.cta_group::1.kind::tf32 [%0], %1, %2, %3, {%4, %4, %4, %4}, pq;\n\t}"
        :: "r"(d_tmem), "l"(ad), "l"(bd), "r"(IDESC_TF32), "r"(0u), "r"(en)
        : "memory");
}
#endif  // __CUDA_ARCH_FEAT_SM103_ALL

// ---------- GEMM: A[M,K] x B[N,K]^T, tile (128*MH)x256, 256 threads ----------
// sm_103a: TMA-fed NS-stage ring tcgen05 SS pipeline. The driver thread issues
// MMA(kt) BEFORE waiting done(kt-1), so MMAs run back-to-back in the tensor
// queue and the refill TMA trails one chunk behind with NS-1 buffers of lead.
// EPI: 0 = plain C write, 1 = QKV scatter. ROUND: round stored values to tf32.
template <int MH, int NS, int EPI, int ROUND>
__global__ void __launch_bounds__(256) gemm_tma(
    const __grid_constant__ CUtensorMap mA,
    const __grid_constant__ CUtensorMap mB,
    GemmParams p)
{
    extern __shared__ __align__(16) float smem_raw[];
    const int tid = threadIdx.x;
    const int lane = tid & 31;
    const int wid = tid >> 5;
    const int bn = blockIdx.x, bm = blockIdx.y, z = blockIdx.z;
    const size_t coff = (size_t)(z / p.divH) * p.strideCb +
                        (size_t)(z % p.divH) * p.strideCh;

#if defined(__CUDA_ARCH_FEAT_SM103_ALL)
    __shared__ uint32_t s_tmem;
    __shared__ __align__(8) unsigned long long s_mbar[2 * NS];  // full[NS], done[NS]

    const uint32_t raw_u  = smem_u32_g(smem_raw);
    const uint32_t smem_u = (raw_u + 1023u) & ~1023u;   // SW128 atom alignment
    const uint32_t mbar   = smem_u32_g(s_mbar);         // full[s]=mbar+8s, done[s]=mbar+8(NS+s)

    constexpr uint32_t ASZ = MH * 16384u;       // A stage bytes
    constexpr uint32_t SZ  = ASZ + 32768u;      // stage bytes (A+B)
    constexpr uint32_t TCOLS = MH * 256u;

    if (wid == 0) { TCGEN05_ALLOC(smem_u32_g(&s_tmem), TCOLS); TCGEN05_RELINQ(); }
    if (tid == 0) {
        #pragma unroll
        for (int s = 0; s < 2 * NS; s++) MBARRIER_INIT(mbar + 8 * s, 1);
        FENCE_ASYNC();
    }
    __syncthreads();
    const uint32_t tmem = s_tmem;

    const int nIter = p.K >> 5;   // 24 / 32 / 288  (always >= NS here)

    if (wid == 0) {
        if (elect_one()) {
            const CUtensorMap* pA = &mA;
            const CUtensorMap* pB = &mB;
            const int m0 = bm * (128 * MH);
            const int n0 = bn * 256;
            int phf[NS], phd[NS];
            #pragma unroll
            for (int s = 0; s < NS; s++) { phf[s] = 0; phd[s] = 0; }

            // Prologue: fill the ring
            const int pre = (nIter < NS) ? nIter : NS;
            for (int s = 0; s < pre; s++) {
                MBARRIER_EXPECT_TX(mbar + 8 * s, SZ);
                TMA3D(smem_u + s * SZ, pA, s * 32, m0, z, mbar + 8 * s);
                TMA3D(smem_u + s * SZ + ASZ, pB, s * 32, n0, z, mbar + 8 * s);
            }

            for (int kt = 0; kt < nIter; kt++) {
                const int b = kt % NS;
                // 1) data ready for this chunk
                MBARRIER_WAIT_PARITY(mbar + 8 * b, phf[b]); phf[b] ^= 1;
                // 2) enqueue MMAs + completion commit (async; engine runs b2b)
                const uint32_t oa = smem_u + b * SZ;
                const uint64_t bd = mk_desc(oa + ASZ);
                #pragma unroll
                for (int ks = 0; ks < 4; ks++) {
                    #pragma unroll
                    for (int mh = 0; mh < MH; mh++) {
                        const uint64_t ad = mk_desc(oa + mh * 16384u);
                        mma_tf32_ss(tmem + mh * 256, ad + ks * 2, bd + ks * 2,
                                    (kt > 0 || ks > 0) ? 1u : 0u);
                    }
                }
                TCGEN05_COMMIT(mbar + 8 * (NS + b));
                // 3) lazily retire chunk kt-1 and refill its buffer for kt-1+NS;
                //    this done-wait overlaps with MMA(kt) executing.
                const int rt = kt - 1;
                if (rt >= 0 && rt + NS < nIter) {
                    const int rb = rt % NS;
                    MBARRIER_WAIT_PARITY(mbar + 8 * (NS + rb), phd[rb]); phd[rb] ^= 1;
                    const uint32_t ra = smem_u + rb * SZ;
                    MBARRIER_EXPECT_TX(mbar + 8 * rb, SZ);
                    TMA3D(ra, pA, (rt + NS) * 32, m0, z, mbar + 8 * rb);
                    TMA3D(ra + ASZ, pB, (rt + NS) * 32, n0, z, mbar + 8 * rb);
                }
            }
            // Drain un-retired done commits: chunks [max(0,nIter-NS-?)..]
            // In-loop we waited done for rt = 0..nIter-NS-1. Remaining:
            // chunks nIter-NS .. nIter-1 (or all if nIter < NS+1).
            int first = nIter - NS;
            if (first < 0) first = 0;
            for (int kt = first; kt < nIter; kt++) {
                const int b = kt % NS;
                MBARRIER_WAIT_PARITY(mbar + 8 * (NS + b), phd[b]); phd[b] ^= 1;
            }
        }
    }
    __syncthreads();
    TCGEN05_FENCE_AFTER();

    // Epilogue.
    // MH=2: warps 0-3 -> M-half 0 (TMEM cols 0-255), warps 4-7 -> M-half 1
    //       (cols 256-511). Each warp: 8 x 32-col slices covering n [0,256).
    // MH=1: warps 0-3 -> cols 0-127, warps 4-7 -> cols 128-255 (4 slices).
    const int nslice = (MH == 2) ? 8 : 4;
    const int m = bm * (128 * MH) +
                  ((MH == 2) ? (wid >> 2) * 128 : 0) + (wid & 3) * 32 + lane;
    const uint32_t tbase = tmem + ((MH == 2) ? (uint32_t)(wid >> 2) * 256u
                                             : (uint32_t)(wid >> 2) * 128u);
    const int nbase = bn * 256 + ((MH == 2) ? 0 : (wid >> 2) * 128);

    for (int i = 0; i < nslice; i++) {
        uint32_t r[32];
        TCGEN05_LD_32X32B_X32(r, tbase + i * 32);
        TCGEN05_WAIT_LD();
        const int n0 = nbase + i * 32;
        float* dst;
        if (EPI == 1) {
            const int b = m >> 10, s = m & 1023;
            const int h = n0 / F3, f = n0 - h * F3;
            dst = &g_qkv[(((size_t)(b * Hn + h)) * Sn + s) * F3 + f];
        } else {
            dst = &p.C[coff + (size_t)m * p.ldc + n0];
        }
        #pragma unroll
        for (int j = 0; j < 32; j += 4) {
            float4 v;
            v.x = __uint_as_float(r[j + 0]) * p.alpha;
            v.y = __uint_as_float(r[j + 1]) * p.alpha;
            v.z = __uint_as_float(r[j + 2]) * p.alpha;
            v.w = __uint_as_float(r[j + 3]) * p.alpha;
            if (p.bias) {
                float4 bb = *(const float4*)&p.bias[n0 + j];
                v.x += bb.x; v.y += bb.y; v.z += bb.z; v.w += bb.w;
            }
            if (ROUND) {
                v.x = __uint_as_float(f2tf32(v.x));
                v.y = __uint_as_float(f2tf32(v.y));
                v.z = __uint_as_float(f2tf32(v.z));
                v.w = __uint_as_float(f2tf32(v.w));
            }
            *(float4*)&dst[j] = v;
        }
    }
    TCGEN05_FENCE_BEFORE();

    __syncthreads();
    if (tid == 0) {
        #pragma unroll
        for (int s = 0; s < 2 * NS; s++) MBARRIER_INVAL(mbar + 8 * s);
    }
    __syncthreads();
    if (wid == 0) TCGEN05_DEALLOC(tmem, TCOLS);

#else
    // Naive correct fallback (never selected when sm_103a SASS is present)
    (void)smem_raw;
    const int MT = 128 * MH;
    for (int o = tid; o < MT * 256; o += 256) {
        const int mi = o >> 8;
        const int ni = o & 255;
        const float* a = p.A + (size_t)z * p.strideAz + (size_t)(bm * MT + mi) * p.lda;
        const float* b = p.B + (size_t)z * p.strideBz + (size_t)(bn * 256 + ni) * p.ldb;
        float acc = 0.f;
        for (int k = 0; k < p.K; k++) acc += a[k] * b[k];
        float v = acc * p.alpha;
        const int n0 = bn * 256 + ni;
        if (p.bias) v += p.bias[n0];
        if (ROUND) v = __uint_as_float(f2tf32(v));
        const int mg = bm * MT + mi;
        if (EPI == 1) {
            const int bb = mg >> 10, s = mg & 1023;
            const int h = n0 / F3, f = n0 - h * F3;
            g_qkv[(((size_t)(bb * Hn + h)) * Sn + s) * F3 + f] = v;
        } else {
            p.C[coff + (size_t)mg * p.ldc + n0] = v;
        }
    }
#endif
}

// Round-copy: dst = tf32_rna(src)
__global__ void __launch_bounds__(256) round_copy(const float* __restrict__ s,
                                                  float* __restrict__ d, int n4)
{
    int i = blockIdx.x * blockDim.x + threadIdx.x;
    if (i < n4) {
        float4 v = ((const float4*)s)[i];
        uint4 o;
        o.x = f2tf32(v.x); o.y = f2tf32(v.y); o.z = f2tf32(v.z); o.w = f2tf32(v.w);
        ((uint4*)d)[i] = o;
    }
}

// Transpose V slab of qkv: vT[bh, e, s] = qkv[bh, s, 2E + e] (already rounded)
__global__ void __launch_bounds__(256) transpose_v()
{
    __shared__ float tile[32][33];
    const int bh = blockIdx.z;
    const int s0 = blockIdx.x * 32;
    const int e0 = blockIdx.y * 32;
    const int tx = threadIdx.x;
    const int ty = threadIdx.y;
    const float* src = g_qkv + ((size_t)bh * Sn) * F3 + 2 * En;
    float* dst = g_vT + ((size_t)bh * En) * Sn;

    #pragma unroll
    for (int j = 0; j < 4; j++)
        tile[ty + 8 * j][tx] = src[(size_t)(s0 + ty + 8 * j) * F3 + e0 + tx];
    __syncthreads();
    #pragma unroll
    for (int j = 0; j < 4; j++)
        dst[(size_t)(e0 + ty + 8 * j) * Sn + s0 + tx] = tile[tx][ty + 8 * j];
}

// Softmax rows; output rounded to tf32 bits (AV GEMM input).
__global__ void __launch_bounds__(256) softmax_kernel(float* sc)
{
    float* row = sc + (size_t)blockIdx.x * Sn;
    const int tid = threadIdx.x;
    const int lane = tid & 31;
    const int wid = tid >> 5;
    __shared__ float red[8];

    float4 v = ((const float4*)row)[tid];
    float m = fmaxf(fmaxf(v.x, v.y), fmaxf(v.z, v.w));
    #pragma unroll
    for (int o = 16; o; o >>= 1) m = fmaxf(m, __shfl_xor_sync(~0u, m, o));
    if (lane == 0) red[wid] = m;
    __syncthreads();
    float bm = red[0];
    #pragma unroll
    for (int i = 1; i < 8; i++) bm = fmaxf(bm, red[i]);
    __syncthreads();

    float4 e;
    e.x = __expf(v.x - bm);
    e.y = __expf(v.y - bm);
    e.z = __expf(v.z - bm);
    e.w = __expf(v.w - bm);
    float s = e.x + e.y + e.z + e.w;
    #pragma unroll
    for (int o = 16; o; o >>= 1) s += __shfl_xor_sync(~0u, s, o);
    if (lane == 0) red[wid] = s;
    __syncthreads();
    float bs = red[0];
    #pragma unroll
    for (int i = 1; i < 8; i++) bs += red[i];
    const float rdiv = __frcp_rn(bs);

    uint4 o;
    o.x = f2tf32(e.x * rdiv);
    o.y = f2tf32(e.y * rdiv);
    o.z = f2tf32(e.z * rdiv);
    o.w = f2tf32(e.w * rdiv);
    ((uint4*)row)[tid] = o;
}

#define SMEM_RING (196608 + 1024)   // 3x64KB (MH2) or 4x48KB (MH1) + align slack

// Host-side tensormap builder via driver entry point (no -lcuda needed)
typedef CUresult (*PFN_encodeTM)(CUtensorMap*, CUtensorMapDataType, cuuint32_t, void*,
                                 const cuuint64_t*, const cuuint64_t*, const cuuint32_t*,
                                 const cuuint32_t*, CUtensorMapInterleave, CUtensorMapSwizzle,
                                 CUtensorMapL2promotion, CUtensorMapFloatOOBfill);

static void make_map(CUtensorMap* m, const void* base,
                     unsigned long long d0, unsigned long long d1, unsigned long long d2,
                     unsigned long long s1b, unsigned long long s2b,
                     unsigned int b0, unsigned int b1)
{
    void* fp = nullptr;
    cudaDriverEntryPointQueryResult st;
    cudaGetDriverEntryPoint("cuTensorMapEncodeTiled", &fp, cudaEnableDefault, &st);
    PFN_encodeTM enc = (PFN_encodeTM)fp;
    cuuint64_t dims[3] = {d0, d1, d2};
    cuuint64_t str[2]  = {s1b, s2b};
    cuuint32_t box[3]  = {b0, b1, 1};
    cuuint32_t es[3]   = {1, 1, 1};
    enc(m, CU_TENSOR_MAP_DATA_TYPE_FLOAT32, 3, (void*)base, dims, str, box, es,
        CU_TENSOR_MAP_INTERLEAVE_NONE, CU_TENSOR_MAP_SWIZZLE_128B,
        CU_TENSOR_MAP_L2_PROMOTION_L2_128B, CU_TENSOR_MAP_FLOAT_OOB_FILL_NONE);
}

extern "C" void kernel_launch(void* const* d_in, const int* in_sizes, int n_in,
                              void* d_out, int out_size)
{
    const float* x     = (const float*)d_in[0];  // [B,S,E]
    const float* qkv_w = (const float*)d_in[1];  // [H,3E,E]
    const float* qkv_b = (const float*)d_in[2];  // [H,3E]
    const float* out_w = (const float*)d_in[3];  // [E,H*E]
    const float* out_b = (const float*)d_in[4];  // [E]
    float* out = (float*)d_out;                  // [B,S,E]

    float *qkv, *scores, *vT, *concat, *xr, *wr, *owr;
    cudaGetSymbolAddress((void**)&qkv,    g_qkv);
    cudaGetSymbolAddress((void**)&scores, g_scores);
    cudaGetSymbolAddress((void**)&vT,     g_vT);
    cudaGetSymbolAddress((void**)&concat, g_concat);
    cudaGetSymbolAddress((void**)&xr,     g_xr);
    cudaGetSymbolAddress((void**)&wr,     g_wqkvr);
    cudaGetSymbolAddress((void**)&owr,    g_owr);

    cudaFuncSetAttribute(gemm_tma<2,3,1,1>, cudaFuncAttributeMaxDynamicSharedMemorySize, SMEM_RING);
    cudaFuncSetAttribute(gemm_tma<2,3,0,0>, cudaFuncAttributeMaxDynamicSharedMemorySize, SMEM_RING);
    cudaFuncSetAttribute(gemm_tma<2,3,0,1>, cudaFuncAttributeMaxDynamicSharedMemorySize, SMEM_RING);
    cudaFuncSetAttribute(gemm_tma<1,4,0,0>, cudaFuncAttributeMaxDynamicSharedMemorySize, SMEM_RING);

    // 0) Pre-round inputs to tf32 bits
    round_copy<<<(Bn*Sn*En/4 + 255)/256, 256>>>(x, xr, Bn*Sn*En/4);
    round_copy<<<(NQKV*En/4 + 255)/256, 256>>>(qkv_w, wr, NQKV*En/4);
    round_copy<<<(En*HE/4 + 255)/256, 256>>>(out_w, owr, En*HE/4);

    // Tensormaps (host-side, capture-safe)
    CUtensorMap mXA, mWB, mQA, mKB, mPA, mVB, mCA, mOB;
    make_map(&mXA, xr,      En, (unsigned long long)Bn*Sn, 1,
             (unsigned long long)En*4, (unsigned long long)Bn*Sn*En*4, 32, 256);
    make_map(&mWB, wr,      En, NQKV, 1,
             (unsigned long long)En*4, (unsigned long long)NQKV*En*4, 32, 256);
    make_map(&mQA, qkv,     En, Sn, Bn*Hn,
             (unsigned long long)F3*4, (unsigned long long)Sn*F3*4, 32, 256);
    make_map(&mKB, qkv+En,  En, Sn, Bn*Hn,
             (unsigned long long)F3*4, (unsigned long long)Sn*F3*4, 32, 256);
    make_map(&mPA, scores,  Sn, Sn, Bn*Hn,
             (unsigned long long)Sn*4, (unsigned long long)Sn*Sn*4, 32, 256);
    make_map(&mVB, vT,      Sn, En, Bn*Hn,
             (unsigned long long)Sn*4, (unsigned long long)En*Sn*4, 32, 256);
    make_map(&mCA, concat,  HE, (unsigned long long)Bn*Sn, 1,
             (unsigned long long)HE*4, (unsigned long long)Bn*Sn*HE*4, 32, 128);
    make_map(&mOB, owr,     HE, En, 1,
             (unsigned long long)HE*4, (unsigned long long)En*HE*4, 32, 256);

    // 1) QKV projection -> scatter [B,H,S,3E], +bias, rounded. 256x256, 3-stage.
    {
        GemmParams p = {};
        p.A = xr; p.B = wr; p.C = qkv;
        p.K = En; p.lda = En; p.ldb = En; p.ldc = 0;
        p.divH = 1; p.bias = qkv_b; p.alpha = 1.0f;
        gemm_tma<2,3,1,1><<<dim3(NQKV/256, (Bn*Sn)/256, 1), 256, SMEM_RING>>>(mXA, mWB, p);
    }

    // 1b) Transpose V slab -> vT [B*H, E, S]
    transpose_v<<<dim3(Sn/32, En/32, Bn*Hn), dim3(32, 8)>>>();

    // 2) Scores: Q x K^T * scale. 256x256, 3-stage.
    {
        GemmParams p = {};
        p.A = qkv; p.B = qkv + En; p.C = scores;
        p.K = En; p.lda = F3; p.ldb = F3; p.ldc = Sn;
        p.strideAz = (long long)Sn*F3; p.strideBz = (long long)Sn*F3;
        p.strideCb = (long long)Sn*Sn; p.divH = 1;
        p.bias = nullptr; p.alpha = 0.036084391824351615f; // 1/sqrt(768)
        gemm_tma<2,3,0,0><<<dim3(Sn/256, Sn/256, Bn*Hn), 256, SMEM_RING>>>(mQA, mKB, p);
    }

    // 3) Softmax rows (rounds output)
    softmax_kernel<<<Bn*Hn*Sn, 256>>>(scores);

    // 4) AV: P x vT^T -> concat, rounded. 256x256, 3-stage.
    {
        GemmParams p = {};
        p.A = scores; p.B = vT; p.C = concat;
        p.K = Sn; p.lda = Sn; p.ldb = Sn; p.ldc = HE;
        p.strideAz = (long long)Sn*Sn; p.strideBz = (long long)En*Sn;
        p.strideCb = (long long)Sn*Hn*En; p.strideCh = En; p.divH = Hn;
        p.bias = nullptr; p.alpha = 1.0f;
        gemm_tma<2,3,0,1><<<dim3(En/256, Sn/256, Bn*Hn), 256, SMEM_RING>>>(mPA, mVB, p);
    }

    // 5) Output projection + bias -> out. 128x256, 4-stage (K=9216: deep loop).
    {
        GemmParams p = {};
        p.A = concat; p.B = owr; p.C = out;
        p.K = HE; p.lda = HE; p.ldb = HE; p.ldc = En;
        p.divH = 1; p.bias = out_b; p.alpha = 1.0f;
        gemm_tma<1,4,0,0><<<dim3(En/256, (Bn*Sn)/128, 1), 256, SMEM_RING>>>(mCA, mOB, p);
    }
}

// round 13
// speedup vs baseline: 1.2951x; 1.2426x over previous
#include <cuda_runtime.h>
#include <cuda.h>
#include <stdint.h>

// Problem constants
#define Bn 8
#define Sn 1024
#define En 768
#define Hn 12
#define F3 2304          // 3*E
#define NQKV 27648       // H*3E
#define HE 9216          // H*E

// Scratch (allocation-free: __device__ globals)
__device__ float g_qkv[(size_t)Bn * Hn * Sn * F3];     // [B,H,S,3E] (tf32-rounded)
__device__ float g_scores[(size_t)Bn * Hn * Sn * Sn];  // [B*H,S,S]
__device__ float g_vT[(size_t)Bn * Hn * En * Sn];      // [B*H,E,S]  (tf32-rounded)
__device__ float g_concat[(size_t)Bn * Sn * Hn * En];  // [B,S,H,E]  (tf32-rounded)
__device__ float g_xr[(size_t)Bn * Sn * En];           // rounded x
__device__ float g_wqkvr[(size_t)NQKV * En];           // rounded qkv_w
__device__ float g_owr[(size_t)En * HE];               // rounded out_w

struct GemmParams {
    const float* A;
    const float* B;
    float* C;
    int K;
    int lda, ldb, ldc;
    long long strideAz, strideBz;
    long long strideCb, strideCh;
    int divH;
    const float* bias;
    float alpha;
};

__device__ __forceinline__ uint32_t f2tf32(float x) {
    uint32_t r;
    asm("cvt.rna.tf32.f32 %0, %1;" : "=r"(r) : "f"(x));
    return r;
}

__device__ __forceinline__ uint32_t smem_u32_g(const void* p) {
    uint32_t a;
    asm("{ .reg .u64 t; cvta.to.shared.u64 t, %1; cvt.u32.u64 %0, t; }"
        : "=r"(a) : "l"(p));
    return a;
}

#if defined(__CUDA_ARCH_FEAT_SM103_ALL)
// ---------- sm_103a-only helpers ----------
__device__ __forceinline__ uint32_t elect_one() {
    uint32_t p;
    asm volatile(
        "{\n\t.reg .pred p;\n\telect.sync _|p, 0xFFFFFFFF;\n\t"
        "selp.b32 %0, 1, 0, p;\n\t}" : "=r"(p));
    return p;
}

#define TCGEN05_ALLOC(a, n) \
    asm volatile("tcgen05.alloc.cta_group::1.sync.aligned.shared::cta.b32 [%0], %1;" \
                 :: "r"(a), "r"(n) : "memory")
#define TCGEN05_DEALLOC(t, n) \
    asm volatile("tcgen05.dealloc.cta_group::1.sync.aligned.b32 %0, %1;" :: "r"(t), "r"(n))
#define TCGEN05_RELINQ() \
    asm volatile("tcgen05.relinquish_alloc_permit.cta_group::1.sync.aligned;")
#define TCGEN05_COMMIT(m) \
    asm volatile("tcgen05.commit.cta_group::1.mbarrier::arrive::one.shared::cluster.b64 [%0];" \
                 :: "r"(m) : "memory")
#define MBARRIER_INIT(m, c) \
    asm volatile("mbarrier.init.shared.b64 [%0], %1;" :: "r"(m), "r"(c) : "memory")
#define MBARRIER_INVAL(m) \
    asm volatile("mbarrier.inval.shared.b64 [%0];" :: "r"(m) : "memory")
#define MBARRIER_EXPECT_TX(m, b) \
    asm volatile("mbarrier.arrive.expect_tx.shared.b64 _, [%0], %1;" \
                 :: "r"(m), "r"(b) : "memory")
#define TCGEN05_FENCE_AFTER()  asm volatile("tcgen05.fence::after_thread_sync;" ::: "memory")
#define TCGEN05_FENCE_BEFORE() asm volatile("tcgen05.fence::before_thread_sync;" ::: "memory")
#define TCGEN05_WAIT_LD()      asm volatile("tcgen05.wait::ld.sync.aligned;" ::: "memory")
#define FENCE_ASYNC()          asm volatile("fence.proxy.async.shared::cta;" ::: "memory")

#define TMA3D(sm, mapp, cx, cy, cz, mb) \
    asm volatile( \
        "cp.async.bulk.tensor.3d.shared::cta.global.tile.mbarrier::complete_tx::bytes " \
        "[%0], [%1, {%2, %3, %4}], [%5];" \
        :: "r"(sm), "l"(mapp), "r"(cx), "r"(cy), "r"(cz), "r"(mb) : "memory")

#define MBARRIER_WAIT_PARITY(mbar_smem_addr, phase_parity) do { \
    uint32_t _mbar = (uint32_t)(mbar_smem_addr); \
    uint32_t _parity = (uint32_t)(phase_parity); \
    uint32_t _done; \
    asm volatile( \
        "{\n\t.reg .pred p;\n\t" \
        "mbarrier.try_wait.parity.acquire.cta.shared::cta.b64 p, [%1], %2;\n\t" \
        "selp.b32 %0, 1, 0, p;\n\t}" \
        : "=r"(_done) : "r"(_mbar), "r"(_parity) : "memory"); \
    if (!_done) { \
        asm volatile( \
            "{\n\t.reg .pred P1;\n\t" \
            "WAIT_LOOP_%=:\n\t" \
            "mbarrier.try_wait.parity.acquire.cta.shared::cta.b64 P1, [%0], %1, 0x989680;\n\t" \
            "@P1 bra.uni WAIT_DONE_%=;\n\t" \
            "bra.uni WAIT_LOOP_%=;\n\t" \
            "WAIT_DONE_%=:\n\t}" \
            :: "r"(_mbar), "r"(_parity) : "memory"); \
    } \
} while (0)

#define TCGEN05_LD_32X32B_X32(r, tmem_addr) \
    asm volatile( \
        "tcgen05.ld.sync.aligned.32x32b.x32.b32 " \
        "{%0, %1, %2, %3, %4, %5, %6, %7, " \
        " %8, %9, %10, %11, %12, %13, %14, %15, " \
        " %16, %17, %18, %19, %20, %21, %22, %23, " \
        " %24, %25, %26, %27, %28, %29, %30, %31}, [%32];" \
        : "=r"((r)[0]),  "=r"((r)[1]),  "=r"((r)[2]),  "=r"((r)[3]), \
          "=r"((r)[4]),  "=r"((r)[5]),  "=r"((r)[6]),  "=r"((r)[7]), \
          "=r"((r)[8]),  "=r"((r)[9]),  "=r"((r)[10]), "=r"((r)[11]), \
          "=r"((r)[12]), "=r"((r)[13]), "=r"((r)[14]), "=r"((r)[15]), \
          "=r"((r)[16]), "=r"((r)[17]), "=r"((r)[18]), "=r"((r)[19]), \
          "=r"((r)[20]), "=r"((r)[21]), "=r"((r)[22]), "=r"((r)[23]), \
          "=r"((r)[24]), "=r"((r)[25]), "=r"((r)[26]), "=r"((r)[27]), \
          "=r"((r)[28]), "=r"((r)[29]), "=r"((r)[30]), "=r"((r)[31]) \
        : "r"(tmem_addr))

// SW128 K-major SMEM descriptor (128B rows): layout=SW128, version=1, SBO=64, LBO=1
static __device__ __forceinline__ uint64_t mk_desc(uint32_t addr) {
    const uint64_t base = (2ULL << 61) | (1ULL << 46) | (64ULL << 32) | (1ULL << 16);
    return base | ((uint64_t)(addr >> 4) & 0x3FFF);
}

// idesc kind::tf32: dtype F32=1 @bit4, atype=btype=TF32=2 @bits7/10,
// N/8 @bit17, M/16 @bit24   (M=128, N=256)
#define IDESC_TF32 ((1u << 4) | (2u << 7) | (2u << 10) | (32u << 17) | (8u << 24))

__device__ __forceinline__ void mma_tf32_ss(uint32_t d_tmem, uint64_t ad, uint64_t bd,
                                            uint32_t en) {
    asm volatile(
        "{\n\t.reg .pred pq;\n\tsetp.ne.u32 pq, %5, 0;\n\t"
        "tcgen05.mma.cta_group::1.kind::tf32 [%0], %1, %2, %3, {%4, %4, %4, %4}, pq;\n\t}"
        :: "r"(d_tmem), "l"(ad), "l"(bd), "r"(IDESC_TF32), "r"(0u), "r"(en)
        : "memory");
}
#endif  // __CUDA_ARCH_FEAT_SM103_ALL

// ---------- GEMM: A[M,K] x B[N,K]^T, tile (128*MH)x256, 256 threads ----------
// sm_103a: TMA-fed NS-stage ring tcgen05 SS pipeline.
// SWAP=1: bm on blockIdx.x (wave spans M tiles -> B reused from L2/DRAM once).
// Epilogue: TMEM slices staged through padded SMEM -> fully coalesced STG rows.
// EPI: 0 = plain C write, 1 = QKV scatter. ROUND: round stored values to tf32.
template <int MH, int NS, int EPI, int ROUND, int SWAP>
__global__ void __launch_bounds__(256) gemm_tma(
    const __grid_constant__ CUtensorMap mA,
    const __grid_constant__ CUtensorMap mB,
    GemmParams p)
{
    extern __shared__ __align__(16) float smem_raw[];
    const int tid = threadIdx.x;
    const int lane = tid & 31;
    const int wid = tid >> 5;
    const int bn = SWAP ? blockIdx.y : blockIdx.x;
    const int bm = SWAP ? blockIdx.x : blockIdx.y;
    const int z  = blockIdx.z;
    const size_t coff = (size_t)(z / p.divH) * p.strideCb +
                        (size_t)(z % p.divH) * p.strideCh;

#if defined(__CUDA_ARCH_FEAT_SM103_ALL)
    __shared__ uint32_t s_tmem;
    __shared__ __align__(8) unsigned long long s_mbar[2 * NS];  // full[NS], done[NS]

    const uint32_t raw_u  = smem_u32_g(smem_raw);
    const uint32_t smem_u = (raw_u + 1023u) & ~1023u;   // SW128 atom alignment
    float* smem_al = (float*)((char*)smem_raw + (smem_u - raw_u));
    const uint32_t mbar   = smem_u32_g(s_mbar);

    constexpr uint32_t ASZ = MH * 16384u;       // A stage bytes
    constexpr uint32_t SZ  = ASZ + 32768u;      // stage bytes (A+B)
    constexpr uint32_t TCOLS = MH * 256u;

    if (wid == 0) { TCGEN05_ALLOC(smem_u32_g(&s_tmem), TCOLS); TCGEN05_RELINQ(); }
    if (tid == 0) {
        #pragma unroll
        for (int s = 0; s < 2 * NS; s++) MBARRIER_INIT(mbar + 8 * s, 1);
        FENCE_ASYNC();
    }
    __syncthreads();
    const uint32_t tmem = s_tmem;

    const int nIter = p.K >> 5;   // 24 / 32 / 288

    if (wid == 0) {
        if (elect_one()) {
            const CUtensorMap* pA = &mA;
            const CUtensorMap* pB = &mB;
            const int m0 = bm * (128 * MH);
            const int n0 = bn * 256;
            int phf[NS], phd[NS];
            #pragma unroll
            for (int s = 0; s < NS; s++) { phf[s] = 0; phd[s] = 0; }

            const int pre = (nIter < NS) ? nIter : NS;
            for (int s = 0; s < pre; s++) {
                MBARRIER_EXPECT_TX(mbar + 8 * s, SZ);
                TMA3D(smem_u + s * SZ, pA, s * 32, m0, z, mbar + 8 * s);
                TMA3D(smem_u + s * SZ + ASZ, pB, s * 32, n0, z, mbar + 8 * s);
            }

            for (int kt = 0; kt < nIter; kt++) {
                const int b = kt % NS;
                MBARRIER_WAIT_PARITY(mbar + 8 * b, phf[b]); phf[b] ^= 1;
                const uint32_t oa = smem_u + b * SZ;
                const uint64_t bd = mk_desc(oa + ASZ);
                #pragma unroll
                for (int ks = 0; ks < 4; ks++) {
                    #pragma unroll
                    for (int mh = 0; mh < MH; mh++) {
                        const uint64_t ad = mk_desc(oa + mh * 16384u);
                        mma_tf32_ss(tmem + mh * 256, ad + ks * 2, bd + ks * 2,
                                    (kt > 0 || ks > 0) ? 1u : 0u);
                    }
                }
                TCGEN05_COMMIT(mbar + 8 * (NS + b));
                const int rt = kt - 1;
                if (rt >= 0 && rt + NS < nIter) {
                    const int rb = rt % NS;
                    MBARRIER_WAIT_PARITY(mbar + 8 * (NS + rb), phd[rb]); phd[rb] ^= 1;
                    const uint32_t ra = smem_u + rb * SZ;
                    MBARRIER_EXPECT_TX(mbar + 8 * rb, SZ);
                    TMA3D(ra, pA, (rt + NS) * 32, m0, z, mbar + 8 * rb);
                    TMA3D(ra + ASZ, pB, (rt + NS) * 32, n0, z, mbar + 8 * rb);
                }
            }
            int first = nIter - NS;
            if (first < 0) first = 0;
            for (int kt = first; kt < nIter; kt++) {
                const int b = kt % NS;
                MBARRIER_WAIT_PARITY(mbar + 8 * (NS + b), phd[b]); phd[b] ^= 1;
            }
        }
    }
    __syncthreads();
    TCGEN05_FENCE_AFTER();

    // ---- Coalesced epilogue via padded SMEM staging ----
    // Warp w owns 32 M-rows; per 32-col slice: LDTM -> SMEM(32x33) -> 32
    // fully-coalesced 128B row stores.
    const int nslice = (MH == 2) ? 8 : 4;
    const int mrow0 = bm * (128 * MH) +
                      ((MH == 2) ? (wid >> 2) * 128 : 0) + (wid & 3) * 32;
    const uint32_t tbase = tmem + ((MH == 2) ? (uint32_t)(wid >> 2) * 256u
                                             : (uint32_t)(wid >> 2) * 128u);
    const int nbase = bn * 256 + ((MH == 2) ? 0 : (wid >> 2) * 128);
    float* stg = smem_al + wid * (33 * 32);

    for (int i = 0; i < nslice; i++) {
        uint32_t r[32];
        TCGEN05_LD_32X32B_X32(r, tbase + i * 32);
        TCGEN05_WAIT_LD();
        #pragma unroll
        for (int j = 0; j < 32; j++) stg[lane * 33 + j] = __uint_as_float(r[j]);
        __syncwarp();

        const int n0 = nbase + i * 32;
        const float bia = p.bias ? __ldg(&p.bias[n0 + lane]) : 0.f;
        float* dst0;
        long long rstride;
        if (EPI == 1) {
            const int b = mrow0 >> 10, s = mrow0 & 1023;
            const int h = n0 / F3, f = n0 - h * F3;
            dst0 = &g_qkv[(((size_t)(b * Hn + h)) * Sn + s) * F3 + f];
            rstride = F3;
        } else {
            dst0 = &p.C[coff + (size_t)mrow0 * p.ldc + n0];
            rstride = p.ldc;
        }
        #pragma unroll 8
        for (int row = 0; row < 32; row++) {
            float v = stg[row * 33 + lane] * p.alpha + bia;
            if (ROUND) v = __uint_as_float(f2tf32(v));
            dst0[(size_t)row * rstride + lane] = v;
        }
        __syncwarp();
    }
    TCGEN05_FENCE_BEFORE();

    __syncthreads();
    if (tid == 0) {
        #pragma unroll
        for (int s = 0; s < 2 * NS; s++) MBARRIER_INVAL(mbar + 8 * s);
    }
    __syncthreads();
    if (wid == 0) TCGEN05_DEALLOC(tmem, TCOLS);

#else
    // Naive correct fallback (never selected when sm_103a SASS is present)
    (void)smem_raw;
    const int MT = 128 * MH;
    for (int o = tid; o < MT * 256; o += 256) {
        const int mi = o >> 8;
        const int ni = o & 255;
        const float* a = p.A + (size_t)z * p.strideAz + (size_t)(bm * MT + mi) * p.lda;
        const float* b = p.B + (size_t)z * p.strideBz + (size_t)(bn * 256 + ni) * p.ldb;
        float acc = 0.f;
        for (int k = 0; k < p.K; k++) acc += a[k] * b[k];
        float v = acc * p.alpha;
        const int n0 = bn * 256 + ni;
        if (p.bias) v += p.bias[n0];
        if (ROUND) v = __uint_as_float(f2tf32(v));
        const int mg = bm * MT + mi;
        if (EPI == 1) {
            const int bb = mg >> 10, s = mg & 1023;
            const int h = n0 / F3, f = n0 - h * F3;
            g_qkv[(((size_t)(bb * Hn + h)) * Sn + s) * F3 + f] = v;
        } else {
            p.C[coff + (size_t)mg * p.ldc + n0] = v;
        }
    }
#endif
}

// Round-copy: dst = tf32_rna(src)
__global__ void __launch_bounds__(256) round_copy(const float* __restrict__ s,
                                                  float* __restrict__ d, int n4)
{
    int i = blockIdx.x * blockDim.x + threadIdx.x;
    if (i < n4) {
        float4 v = ((const float4*)s)[i];
        uint4 o;
        o.x = f2tf32(v.x); o.y = f2tf32(v.y); o.z = f2tf32(v.z); o.w = f2tf32(v.w);
        ((uint4*)d)[i] = o;
    }
}

// Transpose V slab of qkv: vT[bh, e, s] = qkv[bh, s, 2E + e] (already rounded)
__global__ void __launch_bounds__(256) transpose_v()
{
    __shared__ float tile[32][33];
    const int bh = blockIdx.z;
    const int s0 = blockIdx.x * 32;
    const int e0 = blockIdx.y * 32;
    const int tx = threadIdx.x;
    const int ty = threadIdx.y;
    const float* src = g_qkv + ((size_t)bh * Sn) * F3 + 2 * En;
    float* dst = g_vT + ((size_t)bh * En) * Sn;

    #pragma unroll
    for (int j = 0; j < 4; j++)
        tile[ty + 8 * j][tx] = src[(size_t)(s0 + ty + 8 * j) * F3 + e0 + tx];
    __syncthreads();
    #pragma unroll
    for (int j = 0; j < 4; j++)
        dst[(size_t)(e0 + ty + 8 * j) * Sn + s0 + tx] = tile[tx][ty + 8 * j];
}

// Softmax rows; output rounded to tf32 bits (AV GEMM input).
__global__ void __launch_bounds__(256) softmax_kernel(float* sc)
{
    float* row = sc + (size_t)blockIdx.x * Sn;
    const int tid = threadIdx.x;
    const int lane = tid & 31;
    const int wid = tid >> 5;
    __shared__ float red[8];

    float4 v = ((const float4*)row)[tid];
    float m = fmaxf(fmaxf(v.x, v.y), fmaxf(v.z, v.w));
    #pragma unroll
    for (int o = 16; o; o >>= 1) m = fmaxf(m, __shfl_xor_sync(~0u, m, o));
    if (lane == 0) red[wid] = m;
    __syncthreads();
    float bm = red[0];
    #pragma unroll
    for (int i = 1; i < 8; i++) bm = fmaxf(bm, red[i]);
    __syncthreads();

    float4 e;
    e.x = __expf(v.x - bm);
    e.y = __expf(v.y - bm);
    e.z = __expf(v.z - bm);
    e.w = __expf(v.w - bm);
    float s = e.x + e.y + e.z + e.w;
    #pragma unroll
    for (int o = 16; o; o >>= 1) s += __shfl_xor_sync(~0u, s, o);
    if (lane == 0) red[wid] = s;
    __syncthreads();
    float bs = red[0];
    #pragma unroll
    for (int i = 1; i < 8; i++) bs += red[i];
    const float rdiv = __frcp_rn(bs);

    uint4 o;
    o.x = f2tf32(e.x * rdiv);
    o.y = f2tf32(e.y * rdiv);
    o.z = f2tf32(e.z * rdiv);
    o.w = f2tf32(e.w * rdiv);
    ((uint4*)row)[tid] = o;
}

#define SMEM_RING (196608 + 1024)   // 3x64KB (MH2) or 4x48KB (MH1) + align slack

// Host-side tensormap builder via driver entry point (no -lcuda needed)
typedef CUresult (*PFN_encodeTM)(CUtensorMap*, CUtensorMapDataType, cuuint32_t, void*,
                                 const cuuint64_t*, const cuuint64_t*, const cuuint32_t*,
                                 const cuuint32_t*, CUtensorMapInterleave, CUtensorMapSwizzle,
                                 CUtensorMapL2promotion, CUtensorMapFloatOOBfill);

static void make_map(CUtensorMap* m, const void* base,
                     unsigned long long d0, unsigned long long d1, unsigned long long d2,
                     unsigned long long s1b, unsigned long long s2b,
                     unsigned int b0, unsigned int b1)
{
    void* fp = nullptr;
    cudaDriverEntryPointQueryResult st;
    cudaGetDriverEntryPoint("cuTensorMapEncodeTiled", &fp, cudaEnableDefault, &st);
    PFN_encodeTM enc = (PFN_encodeTM)fp;
    cuuint64_t dims[3] = {d0, d1, d2};
    cuuint64_t str[2]  = {s1b, s2b};
    cuuint32_t box[3]  = {b0, b1, 1};
    cuuint32_t es[3]   = {1, 1, 1};
    enc(m, CU_TENSOR_MAP_DATA_TYPE_FLOAT32, 3, (void*)base, dims, str, box, es,
        CU_TENSOR_MAP_INTERLEAVE_NONE, CU_TENSOR_MAP_SWIZZLE_128B,
        CU_TENSOR_MAP_L2_PROMOTION_L2_128B, CU_TENSOR_MAP_FLOAT_OOB_FILL_NONE);
}

extern "C" void kernel_launch(void* const* d_in, const int* in_sizes, int n_in,
                              void* d_out, int out_size)
{
    const float* x     = (const float*)d_in[0];  // [B,S,E]
    const float* qkv_w = (const float*)d_in[1];  // [H,3E,E]
    const float* qkv_b = (const float*)d_in[2];  // [H,3E]
    const float* out_w = (const float*)d_in[3];  // [E,H*E]
    const float* out_b = (const float*)d_in[4];  // [E]
    float* out = (float*)d_out;                  // [B,S,E]

    float *qkv, *scores, *vT, *concat, *xr, *wr, *owr;
    cudaGetSymbolAddress((void**)&qkv,    g_qkv);
    cudaGetSymbolAddress((void**)&scores, g_scores);
    cudaGetSymbolAddress((void**)&vT,     g_vT);
    cudaGetSymbolAddress((void**)&concat, g_concat);
    cudaGetSymbolAddress((void**)&xr,     g_xr);
    cudaGetSymbolAddress((void**)&wr,     g_wqkvr);
    cudaGetSymbolAddress((void**)&owr,    g_owr);

    cudaFuncSetAttribute(gemm_tma<2,3,1,1,1>, cudaFuncAttributeMaxDynamicSharedMemorySize, SMEM_RING);
    cudaFuncSetAttribute(gemm_tma<2,3,0,0,0>, cudaFuncAttributeMaxDynamicSharedMemorySize, SMEM_RING);
    cudaFuncSetAttribute(gemm_tma<2,3,0,1,0>, cudaFuncAttributeMaxDynamicSharedMemorySize, SMEM_RING);
    cudaFuncSetAttribute(gemm_tma<1,4,0,0,0>, cudaFuncAttributeMaxDynamicSharedMemorySize, SMEM_RING);

    // 0) Pre-round inputs to tf32 bits
    round_copy<<<(Bn*Sn*En/4 + 255)/256, 256>>>(x, xr, Bn*Sn*En/4);
    round_copy<<<(NQKV*En/4 + 255)/256, 256>>>(qkv_w, wr, NQKV*En/4);
    round_copy<<<(En*HE/4 + 255)/256, 256>>>(out_w, owr, En*HE/4);

    // Tensormaps (host-side, capture-safe)
    CUtensorMap mXA, mWB, mQA, mKB, mPA, mVB, mCA, mOB;
    make_map(&mXA, xr,      En, (unsigned long long)Bn*Sn, 1,
             (unsigned long long)En*4, (unsigned long long)Bn*Sn*En*4, 32, 256);
    make_map(&mWB, wr,      En, NQKV, 1,
             (unsigned long long)En*4, (unsigned long long)NQKV*En*4, 32, 256);
    make_map(&mQA, qkv,     En, Sn, Bn*Hn,
             (unsigned long long)F3*4, (unsigned long long)Sn*F3*4, 32, 256);
    make_map(&mKB, qkv+En,  En, Sn, Bn*Hn,
             (unsigned long long)F3*4, (unsigned long long)Sn*F3*4, 32, 256);
    make_map(&mPA, scores,  Sn, Sn, Bn*Hn,
             (unsigned long long)Sn*4, (unsigned long long)Sn*Sn*4, 32, 256);
    make_map(&mVB, vT,      Sn, En, Bn*Hn,
             (unsigned long long)Sn*4, (unsigned long long)En*Sn*4, 32, 256);
    make_map(&mCA, concat,  HE, (unsigned long long)Bn*Sn, 1,
             (unsigned long long)HE*4, (unsigned long long)Bn*Sn*HE*4, 32, 128);
    make_map(&mOB, owr,     HE, En, 1,
             (unsigned long long)HE*4, (unsigned long long)En*HE*4, 32, 256);

    // 1) QKV projection -> scatter [B,H,S,3E], +bias, rounded.
    //    SWAP grid: bm on x so each wave spans all M tiles -> W streamed once.
    {
        GemmParams p = {};
        p.A = xr; p.B = wr; p.C = qkv;
        p.K = En; p.lda = En; p.ldb = En; p.ldc = 0;
        p.divH = 1; p.bias = qkv_b; p.alpha = 1.0f;
        gemm_tma<2,3,1,1,1><<<dim3((Bn*Sn)/256, NQKV/256, 1), 256, SMEM_RING>>>(mXA, mWB, p);
    }

    // 1b) Transpose V slab -> vT [B*H, E, S]
    transpose_v<<<dim3(Sn/32, En/32, Bn*Hn), dim3(32, 8)>>>();

    // 2) Scores: Q x K^T * scale. 256x256, 3-stage.
    {
        GemmParams p = {};
        p.A = qkv; p.B = qkv + En; p.C = scores;
        p.K = En; p.lda = F3; p.ldb = F3; p.ldc = Sn;
        p.strideAz = (long long)Sn*F3; p.strideBz = (long long)Sn*F3;
        p.strideCb = (long long)Sn*Sn; p.divH = 1;
        p.bias = nullptr; p.alpha = 0.036084391824351615f; // 1/sqrt(768)
        gemm_tma<2,3,0,0,0><<<dim3(Sn/256, Sn/256, Bn*Hn), 256, SMEM_RING>>>(mQA, mKB, p);
    }

    // 3) Softmax rows (rounds output)
    softmax_kernel<<<Bn*Hn*Sn, 256>>>(scores);

    // 4) AV: P x vT^T -> concat, rounded. 256x256, 3-stage.
    {
        GemmParams p = {};
        p.A = scores; p.B = vT; p.C = concat;
        p.K = Sn; p.lda = Sn; p.ldb = Sn; p.ldc = HE;
        p.strideAz = (long long)Sn*Sn; p.strideBz = (long long)En*Sn;
        p.strideCb = (long long)Sn*Hn*En; p.strideCh = En; p.divH = Hn;
        p.bias = nullptr; p.alpha = 1.0f;
        gemm_tma<2,3,0,1,0><<<dim3(En/256, Sn/256, Bn*Hn), 256, SMEM_RING>>>(mPA, mVB, p);
    }

    // 5) Output projection + bias -> out. 128x256, 4-stage (K=9216: deep loop).
    {
        GemmParams p = {};
        p.A = concat; p.B = owr; p.C = out;
        p.K = HE; p.lda = HE; p.ldb = HE; p.ldc = En;
        p.divH = 1; p.bias = out_b; p.alpha = 1.0f;
        gemm_tma<1,4,0,0,0><<<dim3(En/256, (Bn*Sn)/128, 1), 256, SMEM_RING>>>(mCA, mOB, p);
    }
}

// round 14
// speedup vs baseline: 1.3574x; 1.0481x over previous
#include <cuda_runtime.h>
#include <cuda.h>
#include <stdint.h>

// Problem constants
#define Bn 8
#define Sn 1024
#define En 768
#define Hn 12
#define F3 2304          // 3*E
#define NQKV 27648       // H*3E
#define HE 9216          // H*E

// Scratch (allocation-free: __device__ globals)
__device__ float g_qkv[(size_t)Bn * Hn * Sn * F3];     // [B,H,S,3E] (Q,K slabs used)
__device__ float g_scores[(size_t)Bn * Hn * Sn * Sn];  // [B*H,S,S]
__device__ float g_vT[(size_t)Bn * Hn * En * Sn];      // [B*H,E,S]  (tf32-rounded)
__device__ float g_concat[(size_t)Bn * Sn * Hn * En];  // [B,S,H,E]  (tf32-rounded)
__device__ float g_xr[(size_t)Bn * Sn * En];           // rounded x
__device__ float g_wqkvr[(size_t)NQKV * En];           // rounded qkv_w
__device__ float g_owr[(size_t)En * HE];               // rounded out_w

struct GemmParams {
    const float* A;
    const float* B;
    float* C;
    int K;
    int lda, ldb, ldc;
    long long strideAz, strideBz;
    long long strideCb, strideCh;
    int divH;
    const float* bias;
    float alpha;
};

__device__ __forceinline__ uint32_t f2tf32(float x) {
    uint32_t r;
    asm("cvt.rna.tf32.f32 %0, %1;" : "=r"(r) : "f"(x));
    return r;
}

__device__ __forceinline__ uint32_t smem_u32_g(const void* p) {
    uint32_t a;
    asm("{ .reg .u64 t; cvta.to.shared.u64 t, %1; cvt.u32.u64 %0, t; }"
        : "=r"(a) : "l"(p));
    return a;
}

#if defined(__CUDA_ARCH_FEAT_SM103_ALL)
// ---------- sm_103a-only helpers ----------
__device__ __forceinline__ uint32_t elect_one() {
    uint32_t p;
    asm volatile(
        "{\n\t.reg .pred p;\n\telect.sync _|p, 0xFFFFFFFF;\n\t"
        "selp.b32 %0, 1, 0, p;\n\t}" : "=r"(p));
    return p;
}

#define TCGEN05_ALLOC(a, n) \
    asm volatile("tcgen05.alloc.cta_group::1.sync.aligned.shared::cta.b32 [%0], %1;" \
                 :: "r"(a), "r"(n) : "memory")
#define TCGEN05_DEALLOC(t, n) \
    asm volatile("tcgen05.dealloc.cta_group::1.sync.aligned.b32 %0, %1;" :: "r"(t), "r"(n))
#define TCGEN05_RELINQ() \
    asm volatile("tcgen05.relinquish_alloc_permit.cta_group::1.sync.aligned;")
#define TCGEN05_COMMIT(m) \
    asm volatile("tcgen05.commit.cta_group::1.mbarrier::arrive::one.shared::cluster.b64 [%0];" \
                 :: "r"(m) : "memory")
#define MBARRIER_INIT(m, c) \
    asm volatile("mbarrier.init.shared.b64 [%0], %1;" :: "r"(m), "r"(c) : "memory")
#define MBARRIER_INVAL(m) \
    asm volatile("mbarrier.inval.shared.b64 [%0];" :: "r"(m) : "memory")
#define MBARRIER_EXPECT_TX(m, b) \
    asm volatile("mbarrier.arrive.expect_tx.shared.b64 _, [%0], %1;" \
                 :: "r"(m), "r"(b) : "memory")
#define TCGEN05_FENCE_AFTER()  asm volatile("tcgen05.fence::after_thread_sync;" ::: "memory")
#define TCGEN05_FENCE_BEFORE() asm volatile("tcgen05.fence::before_thread_sync;" ::: "memory")
#define TCGEN05_WAIT_LD()      asm volatile("tcgen05.wait::ld.sync.aligned;" ::: "memory")
#define FENCE_ASYNC()          asm volatile("fence.proxy.async.shared::cta;" ::: "memory")

#define TMA3D(sm, mapp, cx, cy, cz, mb) \
    asm volatile( \
        "cp.async.bulk.tensor.3d.shared::cta.global.tile.mbarrier::complete_tx::bytes " \
        "[%0], [%1, {%2, %3, %4}], [%5];" \
        :: "r"(sm), "l"(mapp), "r"(cx), "r"(cy), "r"(cz), "r"(mb) : "memory")

#define MBARRIER_WAIT_PARITY(mbar_smem_addr, phase_parity) do { \
    uint32_t _mbar = (uint32_t)(mbar_smem_addr); \
    uint32_t _parity = (uint32_t)(phase_parity); \
    uint32_t _done; \
    asm volatile( \
        "{\n\t.reg .pred p;\n\t" \
        "mbarrier.try_wait.parity.acquire.cta.shared::cta.b64 p, [%1], %2;\n\t" \
        "selp.b32 %0, 1, 0, p;\n\t}" \
        : "=r"(_done) : "r"(_mbar), "r"(_parity) : "memory"); \
    if (!_done) { \
        asm volatile( \
            "{\n\t.reg .pred P1;\n\t" \
            "WAIT_LOOP_%=:\n\t" \
            "mbarrier.try_wait.parity.acquire.cta.shared::cta.b64 P1, [%0], %1, 0x989680;\n\t" \
            "@P1 bra.uni WAIT_DONE_%=;\n\t" \
            "bra.uni WAIT_LOOP_%=;\n\t" \
            "WAIT_DONE_%=:\n\t}" \
            :: "r"(_mbar), "r"(_parity) : "memory"); \
    } \
} while (0)

#define TCGEN05_LD_32X32B_X32(r, tmem_addr) \
    asm volatile( \
        "tcgen05.ld.sync.aligned.32x32b.x32.b32 " \
        "{%0, %1, %2, %3, %4, %5, %6, %7, " \
        " %8, %9, %10, %11, %12, %13, %14, %15, " \
        " %16, %17, %18, %19, %20, %21, %22, %23, " \
        " %24, %25, %26, %27, %28, %29, %30, %31}, [%32];" \
        : "=r"((r)[0]),  "=r"((r)[1]),  "=r"((r)[2]),  "=r"((r)[3]), \
          "=r"((r)[4]),  "=r"((r)[5]),  "=r"((r)[6]),  "=r"((r)[7]), \
          "=r"((r)[8]),  "=r"((r)[9]),  "=r"((r)[10]), "=r"((r)[11]), \
          "=r"((r)[12]), "=r"((r)[13]), "=r"((r)[14]), "=r"((r)[15]), \
          "=r"((r)[16]), "=r"((r)[17]), "=r"((r)[18]), "=r"((r)[19]), \
          "=r"((r)[20]), "=r"((r)[21]), "=r"((r)[22]), "=r"((r)[23]), \
          "=r"((r)[24]), "=r"((r)[25]), "=r"((r)[26]), "=r"((r)[27]), \
          "=r"((r)[28]), "=r"((r)[29]), "=r"((r)[30]), "=r"((r)[31]) \
        : "r"(tmem_addr))

// SW128 K-major SMEM descriptor (128B rows): layout=SW128, version=1, SBO=64, LBO=1
static __device__ __forceinline__ uint64_t mk_desc(uint32_t addr) {
    const uint64_t base = (2ULL << 61) | (1ULL << 46) | (64ULL << 32) | (1ULL << 16);
    return base | ((uint64_t)(addr >> 4) & 0x3FFF);
}

// idesc kind::tf32: dtype F32=1 @bit4, atype=btype=TF32=2 @bits7/10,
// N/8 @bit17, M/16 @bit24   (M=128, N=256)
#define IDESC_TF32 ((1u << 4) | (2u << 7) | (2u << 10) | (32u << 17) | (8u << 24))

__device__ __forceinline__ void mma_tf32_ss(uint32_t d_tmem, uint64_t ad, uint64_t bd,
                                            uint32_t en) {
    asm volatile(
        "{\n\t.reg .pred pq;\n\tsetp.ne.u32 pq, %5, 0;\n\t"
        "tcgen05.mma.cta_group::1.kind::tf32 [%0], %1, %2, %3, {%4, %4, %4, %4}, pq;\n\t}"
        :: "r"(d_tmem), "l"(ad), "l"(bd), "r"(IDESC_TF32), "r"(0u), "r"(en)
        : "memory");
}
#endif  // __CUDA_ARCH_FEAT_SM103_ALL

// ---------- GEMM: A[M,K] x B[N,K]^T, tile (128*MH)x256, 256 threads ----------
// sm_103a: TMA-fed NS-stage ring tcgen05 SS pipeline.
// SWAP=1: bm on blockIdx.x (wave spans M tiles -> B streamed from DRAM once).
// Epilogue: TMEM slices staged via padded SMEM -> coalesced 128B row stores.
// EPI=1 (QKV): Q/K slices scatter to g_qkv; V slices written TRANSPOSED into
// g_vT directly (the staged tile gives the transpose for free).
template <int MH, int NS, int EPI, int ROUND, int SWAP>
__global__ void __launch_bounds__(256) gemm_tma(
    const __grid_constant__ CUtensorMap mA,
    const __grid_constant__ CUtensorMap mB,
    GemmParams p)
{
    extern __shared__ __align__(16) float smem_raw[];
    const int tid = threadIdx.x;
    const int lane = tid & 31;
    const int wid = tid >> 5;
    const int bn = SWAP ? blockIdx.y : blockIdx.x;
    const int bm = SWAP ? blockIdx.x : blockIdx.y;
    const int z  = blockIdx.z;
    const size_t coff = (size_t)(z / p.divH) * p.strideCb +
                        (size_t)(z % p.divH) * p.strideCh;

#if defined(__CUDA_ARCH_FEAT_SM103_ALL)
    __shared__ uint32_t s_tmem;
    __shared__ __align__(8) unsigned long long s_mbar[2 * NS];  // full[NS], done[NS]

    const uint32_t raw_u  = smem_u32_g(smem_raw);
    const uint32_t smem_u = (raw_u + 1023u) & ~1023u;   // SW128 atom alignment
    float* smem_al = (float*)((char*)smem_raw + (smem_u - raw_u));
    const uint32_t mbar   = smem_u32_g(s_mbar);

    constexpr uint32_t ASZ = MH * 16384u;       // A stage bytes
    constexpr uint32_t SZ  = ASZ + 32768u;      // stage bytes (A+B)
    constexpr uint32_t TCOLS = MH * 256u;

    if (wid == 0) { TCGEN05_ALLOC(smem_u32_g(&s_tmem), TCOLS); TCGEN05_RELINQ(); }
    if (tid == 0) {
        #pragma unroll
        for (int s = 0; s < 2 * NS; s++) MBARRIER_INIT(mbar + 8 * s, 1);
        FENCE_ASYNC();
    }
    __syncthreads();
    const uint32_t tmem = s_tmem;

    const int nIter = p.K >> 5;   // 24 / 32 / 288

    if (wid == 0) {
        if (elect_one()) {
            const CUtensorMap* pA = &mA;
            const CUtensorMap* pB = &mB;
            const int m0 = bm * (128 * MH);
            const int n0 = bn * 256;
            int phf[NS], phd[NS];
            #pragma unroll
            for (int s = 0; s < NS; s++) { phf[s] = 0; phd[s] = 0; }

            const int pre = (nIter < NS) ? nIter : NS;
            for (int s = 0; s < pre; s++) {
                MBARRIER_EXPECT_TX(mbar + 8 * s, SZ);
                TMA3D(smem_u + s * SZ, pA, s * 32, m0, z, mbar + 8 * s);
                TMA3D(smem_u + s * SZ + ASZ, pB, s * 32, n0, z, mbar + 8 * s);
            }

            for (int kt = 0; kt < nIter; kt++) {
                const int b = kt % NS;
                MBARRIER_WAIT_PARITY(mbar + 8 * b, phf[b]); phf[b] ^= 1;
                const uint32_t oa = smem_u + b * SZ;
                const uint64_t bd = mk_desc(oa + ASZ);
                #pragma unroll
                for (int ks = 0; ks < 4; ks++) {
                    #pragma unroll
                    for (int mh = 0; mh < MH; mh++) {
                        const uint64_t ad = mk_desc(oa + mh * 16384u);
                        mma_tf32_ss(tmem + mh * 256, ad + ks * 2, bd + ks * 2,
                                    (kt > 0 || ks > 0) ? 1u : 0u);
                    }
                }
                TCGEN05_COMMIT(mbar + 8 * (NS + b));
                const int rt = kt - 1;
                if (rt >= 0 && rt + NS < nIter) {
                    const int rb = rt % NS;
                    MBARRIER_WAIT_PARITY(mbar + 8 * (NS + rb), phd[rb]); phd[rb] ^= 1;
                    const uint32_t ra = smem_u + rb * SZ;
                    MBARRIER_EXPECT_TX(mbar + 8 * rb, SZ);
                    TMA3D(ra, pA, (rt + NS) * 32, m0, z, mbar + 8 * rb);
                    TMA3D(ra + ASZ, pB, (rt + NS) * 32, n0, z, mbar + 8 * rb);
                }
            }
            int first = nIter - NS;
            if (first < 0) first = 0;
            for (int kt = first; kt < nIter; kt++) {
                const int b = kt % NS;
                MBARRIER_WAIT_PARITY(mbar + 8 * (NS + b), phd[b]); phd[b] ^= 1;
            }
        }
    }
    __syncthreads();
    TCGEN05_FENCE_AFTER();

    // ---- Coalesced epilogue via padded SMEM staging ----
    const int nslice = (MH == 2) ? 8 : 4;
    const int mrow0 = bm * (128 * MH) +
                      ((MH == 2) ? (wid >> 2) * 128 : 0) + (wid & 3) * 32;
    const uint32_t tbase = tmem + ((MH == 2) ? (uint32_t)(wid >> 2) * 256u
                                             : (uint32_t)(wid >> 2) * 128u);
    const int nbase = bn * 256 + ((MH == 2) ? 0 : (wid >> 2) * 128);
    float* stg = smem_al + wid * (33 * 32);

    for (int i = 0; i < nslice; i++) {
        uint32_t r[32];
        TCGEN05_LD_32X32B_X32(r, tbase + i * 32);
        TCGEN05_WAIT_LD();
        #pragma unroll
        for (int j = 0; j < 32; j++) stg[lane * 33 + j] = __uint_as_float(r[j]);
        __syncwarp();

        const int n0 = nbase + i * 32;

        if (EPI == 1) {
            const int b = mrow0 >> 10, s = mrow0 & 1023;
            const int h = n0 / F3, f = n0 - h * F3;
            if (f >= 2 * En) {
                // V slice: write transposed into g_vT[bh][e][s] (coalesced rows)
                float* dstv = g_vT + (((size_t)(b * Hn + h)) * En + (f - 2 * En)) * Sn + s;
                #pragma unroll 8
                for (int row = 0; row < 32; row++) {
                    float bia = p.bias ? __ldg(&p.bias[n0 + row]) : 0.f;
                    float v = stg[lane * 33 + row] * p.alpha + bia;
                    if (ROUND) v = __uint_as_float(f2tf32(v));
                    dstv[(size_t)row * Sn + lane] = v;
                }
                __syncwarp();
                continue;
            }
        }

        const float bia = p.bias ? __ldg(&p.bias[n0 + lane]) : 0.f;
        float* dst0;
        long long rstride;
        if (EPI == 1) {
            const int b = mrow0 >> 10, s = mrow0 & 1023;
            const int h = n0 / F3, f = n0 - h * F3;
            dst0 = &g_qkv[(((size_t)(b * Hn + h)) * Sn + s) * F3 + f];
            rstride = F3;
        } else {
            dst0 = &p.C[coff + (size_t)mrow0 * p.ldc + n0];
            rstride = p.ldc;
        }
        #pragma unroll 8
        for (int row = 0; row < 32; row++) {
            float v = stg[row * 33 + lane] * p.alpha + bia;
            if (ROUND) v = __uint_as_float(f2tf32(v));
            dst0[(size_t)row * rstride + lane] = v;
        }
        __syncwarp();
    }
    TCGEN05_FENCE_BEFORE();

    __syncthreads();
    if (tid == 0) {
        #pragma unroll
        for (int s = 0; s < 2 * NS; s++) MBARRIER_INVAL(mbar + 8 * s);
    }
    __syncthreads();
    if (wid == 0) TCGEN05_DEALLOC(tmem, TCOLS);

#else
    // Naive correct fallback (never selected when sm_103a SASS is present)
    (void)smem_raw;
    const int MT = 128 * MH;
    for (int o = tid; o < MT * 256; o += 256) {
        const int mi = o >> 8;
        const int ni = o & 255;
        const float* a = p.A + (size_t)z * p.strideAz + (size_t)(bm * MT + mi) * p.lda;
        const float* b = p.B + (size_t)z * p.strideBz + (size_t)(bn * 256 + ni) * p.ldb;
        float acc = 0.f;
        for (int k = 0; k < p.K; k++) acc += a[k] * b[k];
        float v = acc * p.alpha;
        const int n0 = bn * 256 + ni;
        if (p.bias) v += p.bias[n0];
        if (ROUND) v = __uint_as_float(f2tf32(v));
        const int mg = bm * MT + mi;
        if (EPI == 1) {
            const int bb = mg >> 10, s = mg & 1023;
            const int h = n0 / F3, f = n0 - h * F3;
            if (f >= 2 * En)
                g_vT[(((size_t)(bb * Hn + h)) * En + (f - 2 * En)) * Sn + s] = v;
            else
                g_qkv[(((size_t)(bb * Hn + h)) * Sn + s) * F3 + f] = v;
        } else {
            p.C[coff + (size_t)mg * p.ldc + n0] = v;
        }
    }
#endif
}

// Round-copy: dst = tf32_rna(src)
__global__ void __launch_bounds__(256) round_copy(const float* __restrict__ s,
                                                  float* __restrict__ d, int n4)
{
    int i = blockIdx.x * blockDim.x + threadIdx.x;
    if (i < n4) {
        float4 v = ((const float4*)s)[i];
        uint4 o;
        o.x = f2tf32(v.x); o.y = f2tf32(v.y); o.z = f2tf32(v.z); o.w = f2tf32(v.w);
        ((uint4*)d)[i] = o;
    }
}

// Softmax rows; output rounded to tf32 bits (AV GEMM input).
__global__ void __launch_bounds__(256) softmax_kernel(float* sc)
{
    float* row = sc + (size_t)blockIdx.x * Sn;
    const int tid = threadIdx.x;
    const int lane = tid & 31;
    const int wid = tid >> 5;
    __shared__ float red[8];

    float4 v = ((const float4*)row)[tid];
    float m = fmaxf(fmaxf(v.x, v.y), fmaxf(v.z, v.w));
    #pragma unroll
    for (int o = 16; o; o >>= 1) m = fmaxf(m, __shfl_xor_sync(~0u, m, o));
    if (lane == 0) red[wid] = m;
    __syncthreads();
    float bm = red[0];
    #pragma unroll
    for (int i = 1; i < 8; i++) bm = fmaxf(bm, red[i]);
    __syncthreads();

    float4 e;
    e.x = __expf(v.x - bm);
    e.y = __expf(v.y - bm);
    e.z = __expf(v.z - bm);
    e.w = __expf(v.w - bm);
    float s = e.x + e.y + e.z + e.w;
    #pragma unroll
    for (int o = 16; o; o >>= 1) s += __shfl_xor_sync(~0u, s, o);
    if (lane == 0) red[wid] = s;
    __syncthreads();
    float bs = red[0];
    #pragma unroll
    for (int i = 1; i < 8; i++) bs += red[i];
    const float rdiv = __frcp_rn(bs);

    uint4 o;
    o.x = f2tf32(e.x * rdiv);
    o.y = f2tf32(e.y * rdiv);
    o.z = f2tf32(e.z * rdiv);
    o.w = f2tf32(e.w * rdiv);
    ((uint4*)row)[tid] = o;
}

#define SMEM_RING (196608 + 1024)   // 3x64KB + align slack

// Host-side tensormap builder via driver entry point (no -lcuda needed)
typedef CUresult (*PFN_encodeTM)(CUtensorMap*, CUtensorMapDataType, cuuint32_t, void*,
                                 const cuuint64_t*, const cuuint64_t*, const cuuint32_t*,
                                 const cuuint32_t*, CUtensorMapInterleave, CUtensorMapSwizzle,
                                 CUtensorMapL2promotion, CUtensorMapFloatOOBfill);

static void make_map(CUtensorMap* m, const void* base,
                     unsigned long long d0, unsigned long long d1, unsigned long long d2,
                     unsigned long long s1b, unsigned long long s2b,
                     unsigned int b0, unsigned int b1)
{
    void* fp = nullptr;
    cudaDriverEntryPointQueryResult st;
    cudaGetDriverEntryPoint("cuTensorMapEncodeTiled", &fp, cudaEnableDefault, &st);
    PFN_encodeTM enc = (PFN_encodeTM)fp;
    cuuint64_t dims[3] = {d0, d1, d2};
    cuuint64_t str[2]  = {s1b, s2b};
    cuuint32_t box[3]  = {b0, b1, 1};
    cuuint32_t es[3]   = {1, 1, 1};
    enc(m, CU_TENSOR_MAP_DATA_TYPE_FLOAT32, 3, (void*)base, dims, str, box, es,
        CU_TENSOR_MAP_INTERLEAVE_NONE, CU_TENSOR_MAP_SWIZZLE_128B,
        CU_TENSOR_MAP_L2_PROMOTION_L2_128B, CU_TENSOR_MAP_FLOAT_OOB_FILL_NONE);
}

extern "C" void kernel_launch(void* const* d_in, const int* in_sizes, int n_in,
                              void* d_out, int out_size)
{
    const float* x     = (const float*)d_in[0];  // [B,S,E]
    const float* qkv_w = (const float*)d_in[1];  // [H,3E,E]
    const float* qkv_b = (const float*)d_in[2];  // [H,3E]
    const float* out_w = (const float*)d_in[3];  // [E,H*E]
    const float* out_b = (const float*)d_in[4];  // [E]
    float* out = (float*)d_out;                  // [B,S,E]

    float *qkv, *scores, *vT, *concat, *xr, *wr, *owr;
    cudaGetSymbolAddress((void**)&qkv,    g_qkv);
    cudaGetSymbolAddress((void**)&scores, g_scores);
    cudaGetSymbolAddress((void**)&vT,     g_vT);
    cudaGetSymbolAddress((void**)&concat, g_concat);
    cudaGetSymbolAddress((void**)&xr,     g_xr);
    cudaGetSymbolAddress((void**)&wr,     g_wqkvr);
    cudaGetSymbolAddress((void**)&owr,    g_owr);

    cudaFuncSetAttribute(gemm_tma<2,3,1,1,1>, cudaFuncAttributeMaxDynamicSharedMemorySize, SMEM_RING);
    cudaFuncSetAttribute(gemm_tma<2,3,0,0,0>, cudaFuncAttributeMaxDynamicSharedMemorySize, SMEM_RING);
    cudaFuncSetAttribute(gemm_tma<2,3,0,1,0>, cudaFuncAttributeMaxDynamicSharedMemorySize, SMEM_RING);

    // 0) Pre-round inputs to tf32 bits
    round_copy<<<(Bn*Sn*En/4 + 255)/256, 256>>>(x, xr, Bn*Sn*En/4);
    round_copy<<<(NQKV*En/4 + 255)/256, 256>>>(qkv_w, wr, NQKV*En/4);
    round_copy<<<(En*HE/4 + 255)/256, 256>>>(out_w, owr, En*HE/4);

    // Tensormaps (host-side, capture-safe)
    CUtensorMap mXA, mWB, mQA, mKB, mPA, mVB, mCA, mOB;
    make_map(&mXA, xr,      En, (unsigned long long)Bn*Sn, 1,
             (unsigned long long)En*4, (unsigned long long)Bn*Sn*En*4, 32, 256);
    make_map(&mWB, wr,      En, NQKV, 1,
             (unsigned long long)En*4, (unsigned long long)NQKV*En*4, 32, 256);
    make_map(&mQA, qkv,     En, Sn, Bn*Hn,
             (unsigned long long)F3*4, (unsigned long long)Sn*F3*4, 32, 256);
    make_map(&mKB, qkv+En,  En, Sn, Bn*Hn,
             (unsigned long long)F3*4, (unsigned long long)Sn*F3*4, 32, 256);
    make_map(&mPA, scores,  Sn, Sn, Bn*Hn,
             (unsigned long long)Sn*4, (unsigned long long)Sn*Sn*4, 32, 256);
    make_map(&mVB, vT,      Sn, En, Bn*Hn,
             (unsigned long long)Sn*4, (unsigned long long)En*Sn*4, 32, 256);
    make_map(&mCA, concat,  HE, (unsigned long long)Bn*Sn, 1,
             (unsigned long long)HE*4, (unsigned long long)Bn*Sn*HE*4, 32, 256);
    make_map(&mOB, owr,     HE, En, 1,
             (unsigned long long)HE*4, (unsigned long long)En*HE*4, 32, 256);

    // 1) QKV projection -> Q,K scatter to [B,H,S,3E]; V written transposed to vT.
    //    SWAP grid: bm on x so each wave spans all M tiles -> W streamed once.
    {
        GemmParams p = {};
        p.A = xr; p.B = wr; p.C = qkv;
        p.K = En; p.lda = En; p.ldb = En; p.ldc = 0;
        p.divH = 1; p.bias = qkv_b; p.alpha = 1.0f;
        gemm_tma<2,3,1,1,1><<<dim3((Bn*Sn)/256, NQKV/256, 1), 256, SMEM_RING>>>(mXA, mWB, p);
    }

    // 2) Scores: Q x K^T * scale. 256x256, 3-stage.
    {
        GemmParams p = {};
        p.A = qkv; p.B = qkv + En; p.C = scores;
        p.K = En; p.lda = F3; p.ldb = F3; p.ldc = Sn;
        p.strideAz = (long long)Sn*F3; p.strideBz = (long long)Sn*F3;
        p.strideCb = (long long)Sn*Sn; p.divH = 1;
        p.bias = nullptr; p.alpha = 0.036084391824351615f; // 1/sqrt(768)
        gemm_tma<2,3,0,0,0><<<dim3(Sn/256, Sn/256, Bn*Hn), 256, SMEM_RING>>>(mQA, mKB, p);
    }

    // 3) Softmax rows (rounds output)
    softmax_kernel<<<Bn*Hn*Sn, 256>>>(scores);

    // 4) AV: P x vT^T -> concat, rounded. 256x256, 3-stage.
    {
        GemmParams p = {};
        p.A = scores; p.B = vT; p.C = concat;
        p.K = Sn; p.lda = Sn; p.ldb = Sn; p.ldc = HE;
        p.strideAz = (long long)Sn*Sn; p.strideBz = (long long)En*Sn;
        p.strideCb = (long long)Sn*Hn*En; p.strideCh = En; p.divH = Hn;
        p.bias = nullptr; p.alpha = 1.0f;
        gemm_tma<2,3,0,1,0><<<dim3(En/256, Sn/256, Bn*Hn), 256, SMEM_RING>>>(mPA, mVB, p);
    }

    // 5) Output projection + bias -> out. 256x256 tiles: 96 CTAs = ONE wave
    //    (kills the 2-wave quantization of the old 192-CTA launch).
    {
        GemmParams p = {};
        p.A = concat; p.B = owr; p.C = out;
        p.K = HE; p.lda = HE; p.ldb = HE; p.ldc = En;
        p.divH = 1; p.bias = out_b; p.alpha = 1.0f;
        gemm_tma<2,3,0,0,0><<<dim3(En/256, (Bn*Sn)/256, 1), 256, SMEM_RING>>>(mCA, mOB, p);
    }
}